// round 7
// baseline (speedup 1.0000x reference)
#include <cuda_runtime.h>
#include <cuda_bf16.h>
#include <math.h>
#include <stdint.h>

#define Bq 128
#define Lq 64
#define Tq 48
#define Eq 512
#define Hq 512
#define Vq 32000
#define G4 2048
#define KP 512
#define NTILES 250           // logits N tiles (32000/128)
#define LSTRIDE 72
#define HB (Bq * Hq)
#define NLBLK 132            // logits group size

// ---------------- fp32 scratch ----------------
__device__ float g_G0[Bq * Lq * G4];
__device__ float g_c1[HB], g_c2[HB];
__device__ float g_S[Bq * Lq * Hq];
__device__ float g_dh[HB], g_dc[HB];
__device__ float g_nllbuf[(Tq - 1) * Bq];
__device__ float g_part[NTILES * Bq];
__device__ float g_tgtlogit[Bq];

// ---------------- bf16 weights ----------------
__device__ __nv_bfloat16 g_Wih0b[G4 * KP], g_Whh0b[G4 * KP];
__device__ __nv_bfloat16 g_Wih1b[G4 * KP], g_Whh1b[G4 * KP];
__device__ __nv_bfloat16 g_dWihb[G4 * 1024], g_dWhhb[G4 * KP];
__device__ __nv_bfloat16 g_hidWb[Hq * 1024], g_initWb[Hq * 1024];
__device__ __nv_bfloat16 g_srcEmbB[Vq * Eq], g_trgEmbB[Vq * Eq];
__device__ __nv_bfloat16 g_outWb[Vq * KP];

// ---------------- bf16 states ----------------
__device__ __nv_bfloat16 g_h1b[2][HB], g_h2b[2][HB], g_dhb[2][HB];
__device__ __nv_bfloat16 g_nh1b[HB];
__device__ __nv_bfloat16 g_c1b[HB], g_c2b[HB];
__device__ __nv_bfloat16 g_ctxb[HB];
__device__ __nv_bfloat16 g_avh[2][HB];

// ---------------- sync state (zeroed each launch) ----------------
// [0]=enc bar, [8]=decR bar, [16]=decL bar, [24]=r_done, [32]=l_done
__device__ __align__(128) unsigned g_sync[64];

// ---------------- MMA helpers ----------------
__device__ __forceinline__ void ldsm4(unsigned int* r, unsigned int addr) {
    asm volatile("ldmatrix.sync.aligned.m8n8.x4.shared.b16 {%0,%1,%2,%3}, [%4];"
                 : "=r"(r[0]), "=r"(r[1]), "=r"(r[2]), "=r"(r[3]) : "r"(addr));
}
__device__ __forceinline__ void ldsm2(unsigned int* r, unsigned int addr) {
    asm volatile("ldmatrix.sync.aligned.m8n8.x2.shared.b16 {%0,%1}, [%2];"
                 : "=r"(r[0]), "=r"(r[1]) : "r"(addr));
}
__device__ __forceinline__ void mma16816(float* c, const unsigned int* a, const unsigned int* b) {
    asm volatile("mma.sync.aligned.m16n8k16.row.col.f32.bf16.bf16.f32 "
                 "{%0,%1,%2,%3}, {%4,%5,%6,%7}, {%8,%9}, {%0,%1,%2,%3};"
                 : "+f"(c[0]), "+f"(c[1]), "+f"(c[2]), "+f"(c[3])
                 : "r"(a[0]), "r"(a[1]), "r"(a[2]), "r"(a[3]), "r"(b[0]), "r"(b[1]));
}

// ---------------- barriers / flags ----------------
__device__ __forceinline__ void gbar(unsigned* cnt, unsigned target) {
    __threadfence();
    __syncthreads();
    if (threadIdx.x == 0) {
        atomicAdd(cnt, 1u);
        while (*((volatile unsigned*)cnt) < target) __nanosleep(32);
    }
    __syncthreads();
    __threadfence();
}
__device__ __forceinline__ void wait_ge(unsigned* flag, unsigned v) {
    if (threadIdx.x == 0) {
        while (*((volatile unsigned*)flag) < v) __nanosleep(64);
    }
    __syncthreads();
    __threadfence();
}
__device__ __forceinline__ void set_flag(unsigned* flag, unsigned v) {
    __threadfence();
    atomicMax(flag, v);
}

// ============================================================
// gates-layout MMA: M=128, this block's 32 cols of each of 4 gates.
// B tile row r <-> W row (r>>5)*512 + nbase + (r&31). ni fragment = gate.
// A loads bypass L1 (__ldcg): cross-block state inside persistent kernels.
// ============================================================
__device__ __forceinline__ void gates_mma(
    float c[4][4][4],
    const __nv_bfloat16* A0, const int* map0, int ms0, const __nv_bfloat16* W0, int ldw0,
    const __nv_bfloat16* A1, const __nv_bfloat16* W1, int ldw1,
    const __nv_bfloat16* A2, const __nv_bfloat16* W2, int ldw2,
    int npairs, int nbase,
    __nv_bfloat16* As, __nv_bfloat16* Bs)
{
    const int tid = threadIdx.x;
    const int lane = tid & 31;
    const int wid = tid >> 5;
    const int m0 = (wid >> 2) * 64;
    const int warp_n = wid & 3;

#pragma unroll
    for (int mi = 0; mi < 4; mi++)
#pragma unroll
        for (int ni = 0; ni < 4; ni++)
#pragma unroll
            for (int q = 0; q < 4; q++) c[mi][ni][q] = 0.f;

    const unsigned as_base = (unsigned)__cvta_generic_to_shared(As);
    const unsigned bs_base = (unsigned)__cvta_generic_to_shared(Bs);
    const int ldrow = tid >> 3;
    const int ldc8 = (tid & 7) * 8;

    const __nv_bfloat16* Aps[3] = {A0, A1, A2};
    const __nv_bfloat16* Wps[3] = {W0, W1, W2};
    const int lws[3] = {ldw0, ldw1, ldw2};

    for (int p = 0; p < npairs; p++) {
        const __nv_bfloat16* A = Aps[p];
        const __nv_bfloat16* W = Wps[p];
        const int ldw = lws[p];
        for (int kc = 0; kc < 8; kc++) {
            int k0 = kc * 64;
            __syncthreads();
#pragma unroll
            for (int q4 = 0; q4 < 4; q4++) {
                int row = q4 * 32 + ldrow;
                long arow = (p == 0 && map0) ? (long)map0[row * ms0] * 512 : (long)row * 512;
                *reinterpret_cast<uint4*>(&As[row * LSTRIDE + ldc8]) =
                    __ldcg(reinterpret_cast<const uint4*>(&A[arow + k0 + ldc8]));
                int wrow = ((row >> 5) * 512) + nbase + (row & 31);
                *reinterpret_cast<uint4*>(&Bs[row * LSTRIDE + ldc8]) =
                    __ldg(reinterpret_cast<const uint4*>(&W[(long)wrow * ldw + k0 + ldc8]));
            }
            __syncthreads();
#pragma unroll
            for (int ks = 0; ks < 4; ks++) {
                int koff = ks * 16;
                unsigned int a[4][4], b[4][2];
#pragma unroll
                for (int mi = 0; mi < 4; mi++) {
                    int r = m0 + mi * 16 + (lane & 15);
                    int ccol = koff + (lane >> 4) * 8;
                    ldsm4(a[mi], as_base + (unsigned)(r * LSTRIDE + ccol) * 2u);
                }
#pragma unroll
                for (int ni = 0; ni < 4; ni++) {
                    int r = ni * 32 + warp_n * 8 + (lane & 7);
                    int ccol = koff + ((lane >> 3) & 1) * 8;
                    ldsm2(b[ni], bs_base + (unsigned)(r * LSTRIDE + ccol) * 2u);
                }
#pragma unroll
                for (int mi = 0; mi < 4; mi++)
#pragma unroll
                    for (int ni = 0; ni < 4; ni++) mma16816(c[mi][ni], a[mi], b[ni]);
            }
        }
    }
}

// ---------------- LSTM cell epilogue (4 gates in-thread) ----------------
__device__ __forceinline__ void cell_epi(
    float c[4][4][4], int nbase,
    const float* initp, long initStride, const float* bias,
    const int* lens, int t,
    const __nv_bfloat16* hbf_in, __nv_bfloat16* hbf_out,
    float* c_f, __nv_bfloat16* nh_bf_out, float* S_out, float* h_f_out)
{
    const int lane = threadIdx.x & 31;
    const int wid = threadIdx.x >> 5;
    const int m0 = (wid >> 2) * 64;
    const int warp_n = wid & 3;

#pragma unroll
    for (int mi = 0; mi < 4; mi++) {
#pragma unroll
        for (int t2 = 0; t2 < 2; t2++) {
            int row = m0 + mi * 16 + (lane >> 2) + 8 * t2;
#pragma unroll
            for (int u = 0; u < 2; u++) {
                int j = nbase + warp_n * 8 + 2 * (lane & 3) + u;
                int e = 2 * t2 + u;
                float gi = c[mi][0][e], gf = c[mi][1][e], gg = c[mi][2][e], go = c[mi][3][e];
                if (initp) {
                    const float* ip = initp + (long)row * initStride;
                    gi += ip[j]; gf += ip[512 + j]; gg += ip[1024 + j]; go += ip[1536 + j];
                }
                if (bias) {
                    gi += bias[j]; gf += bias[512 + j]; gg += bias[1024 + j]; go += bias[1536 + j];
                }
                float i_ = 1.f / (1.f + expf(-gi));
                float f_ = 1.f / (1.f + expf(-gf));
                float tg = tanhf(gg);
                float o_ = 1.f / (1.f + expf(-go));
                int idx = row * 512 + j;
                float cn = f_ * c_f[idx] + i_ * tg;
                float hn = o_ * tanhf(cn);
                bool mk = lens ? (t < lens[row]) : true;
                if (nh_bf_out) nh_bf_out[idx] = __float2bfloat16_rn(hn);
                if (S_out) S_out[(long)row * Lq * 512 + (long)t * 512 + j] = mk ? hn : 0.f;
                if (h_f_out) h_f_out[idx] = hn;
                if (mk) { c_f[idx] = cn; hbf_out[idx] = __float2bfloat16_rn(hn); }
                else hbf_out[idx] = hbf_in[idx];
            }
        }
    }
}

// ---------------- 128x128 HMMA tile (for hid inside persistent kernel) ----------------
__device__ __forceinline__ void hgemm_tile(
    float c[4][4][4],
    const __nv_bfloat16* A0, const __nv_bfloat16* W0, int ldw0,
    const __nv_bfloat16* A1, const __nv_bfloat16* W1, int ldw1,
    int nblk0, __nv_bfloat16* As, __nv_bfloat16* Bs)
{
    const int tid = threadIdx.x;
    const int lane = tid & 31;
    const int wid = tid >> 5;
    const int m0 = (wid >> 2) * 64;
    const int warp_n = wid & 3;

#pragma unroll
    for (int mi = 0; mi < 4; mi++)
#pragma unroll
        for (int ni = 0; ni < 4; ni++)
#pragma unroll
            for (int q = 0; q < 4; q++) c[mi][ni][q] = 0.f;

    const unsigned as_base = (unsigned)__cvta_generic_to_shared(As);
    const unsigned bs_base = (unsigned)__cvta_generic_to_shared(Bs);
    const int ldrow = tid >> 3;
    const int ldc8 = (tid & 7) * 8;

    const __nv_bfloat16* Aps[2] = {A0, A1};
    const __nv_bfloat16* Wps[2] = {W0, W1};
    const int lws[2] = {ldw0, ldw1};

    for (int p = 0; p < 2; p++) {
        const __nv_bfloat16* A = Aps[p];
        const __nv_bfloat16* W = Wps[p];
        const int ldw = lws[p];
        for (int kc = 0; kc < 8; kc++) {
            int k0 = kc * 64;
            __syncthreads();
#pragma unroll
            for (int q4 = 0; q4 < 4; q4++) {
                int row = q4 * 32 + ldrow;
                *reinterpret_cast<uint4*>(&As[row * LSTRIDE + ldc8]) =
                    __ldcg(reinterpret_cast<const uint4*>(&A[(long)row * 512 + k0 + ldc8]));
                *reinterpret_cast<uint4*>(&Bs[row * LSTRIDE + ldc8]) =
                    __ldg(reinterpret_cast<const uint4*>(&W[(long)(nblk0 + row) * ldw + k0 + ldc8]));
            }
            __syncthreads();
#pragma unroll
            for (int ks = 0; ks < 4; ks++) {
                int koff = ks * 16;
                unsigned int a[4][4], b[4][2];
#pragma unroll
                for (int mi = 0; mi < 4; mi++) {
                    int r = m0 + mi * 16 + (lane & 15);
                    int ccol = koff + (lane >> 4) * 8;
                    ldsm4(a[mi], as_base + (unsigned)(r * LSTRIDE + ccol) * 2u);
                }
#pragma unroll
                for (int ni = 0; ni < 4; ni++) {
                    int r = warp_n * 32 + ni * 8 + (lane & 7);
                    int ccol = koff + ((lane >> 3) & 1) * 8;
                    ldsm2(b[ni], bs_base + (unsigned)(r * LSTRIDE + ccol) * 2u);
                }
#pragma unroll
                for (int mi = 0; mi < 4; mi++)
#pragma unroll
                    for (int ni = 0; ni < 4; ni++) mma16816(c[mi][ni], a[mi], b[ni]);
            }
        }
    }
}

__device__ __forceinline__ void hid_epi(
    float c[4][4][4], int nblk0, const float* bias, __nv_bfloat16* outBF)
{
    const int lane = threadIdx.x & 31;
    const int wid = threadIdx.x >> 5;
    const int m0 = (wid >> 2) * 64;
    const int warp_n = wid & 3;
#pragma unroll
    for (int mi = 0; mi < 4; mi++)
#pragma unroll
        for (int ni = 0; ni < 4; ni++)
#pragma unroll
            for (int t2 = 0; t2 < 2; t2++) {
                int gm = m0 + mi * 16 + (lane >> 2) + 8 * t2;
#pragma unroll
                for (int u = 0; u < 2; u++) {
                    int n = nblk0 + warp_n * 32 + ni * 8 + 2 * (lane & 3) + u;
                    float v = c[mi][ni][2 * t2 + u] + bias[n];
                    outBF[(long)gm * Hq + n] = __float2bfloat16_rn(v);
                }
            }
}

// ---------------- attention: 8 batch rows per block ----------------
__device__ void attn8(int rb0, const int* slens, char* raw)
{
    float* sh = (float*)raw;        // 512
    float* part = sh + 512;         // 256
    float* sc = part + 256;         // 64
    float* sinv = sc + 64;          // 1
    int tid = threadIdx.x;
    for (int r = 0; r < 8; r++) {
        int b = rb0 + r;
        __syncthreads();
        sh[tid] = __ldcg(&g_dh[(long)b * Hq + tid]);
        sh[tid + 256] = __ldcg(&g_dh[(long)b * Hq + tid + 256]);
        __syncthreads();
        int l = tid >> 2, q = tid & 3;
        const float* Sb = g_S + (long)b * Lq * Hq + (long)l * Hq + q * 128;
        float pv = 0.f;
#pragma unroll 8
        for (int k = 0; k < 128; k++) pv = fmaf(sh[q * 128 + k], Sb[k], pv);
        part[l * 4 + q] = pv;
        __syncthreads();
        if (tid < Lq) {
            float sv = part[tid * 4] + part[tid * 4 + 1] + part[tid * 4 + 2] + part[tid * 4 + 3];
            if (tid >= slens[b]) sv = -1e9f;
            sc[tid] = __expf(sv);
        }
        __syncthreads();
        if (tid == 0) {
            float ts = 0.f;
            for (int i = 0; i < Lq; i++) ts += sc[i];
            *sinv = 1.f / ts;
        }
        __syncthreads();
        if (tid < Lq) sc[tid] *= *sinv;
        __syncthreads();
        for (int j = tid; j < Hq; j += 256) {
            const float* Sb2 = g_S + (long)b * Lq * Hq + j;
            float acc = 0.f;
#pragma unroll 8
            for (int l2 = 0; l2 < Lq; l2++) acc = fmaf(sc[l2], Sb2[(long)l2 * Hq], acc);
            g_ctxb[(long)b * Hq + j] = __float2bfloat16_rn(acc);
        }
    }
}

// ---------------- logits tile: GEMM + bias + exp-sum + target capture ----------------
__device__ void logits_tile(
    int tl, const __nv_bfloat16* avh, const float* out_b,
    const int* stgt, float* red, __nv_bfloat16* As, __nv_bfloat16* Bs)
{
    const int tid = threadIdx.x;
    const int lane = tid & 31;
    const int wid = tid >> 5;
    const int m0 = (wid >> 2) * 64;
    const int warp_n = wid & 3;
    const int n0w = warp_n * 32;
    const int nblk0 = tl * 128;

    float c[4][4][4];
#pragma unroll
    for (int mi = 0; mi < 4; mi++)
#pragma unroll
        for (int ni = 0; ni < 4; ni++)
#pragma unroll
            for (int q = 0; q < 4; q++) c[mi][ni][q] = 0.f;

    const unsigned as_base = (unsigned)__cvta_generic_to_shared(As);
    const unsigned bs_base = (unsigned)__cvta_generic_to_shared(Bs);
    const int ldrow = tid >> 3;
    const int ldc8 = (tid & 7) * 8;

    for (int kc = 0; kc < 8; kc++) {
        int k0 = kc * 64;
        __syncthreads();
#pragma unroll
        for (int q4 = 0; q4 < 4; q4++) {
            int row = q4 * 32 + ldrow;
            *reinterpret_cast<uint4*>(&As[row * LSTRIDE + ldc8]) =
                __ldcg(reinterpret_cast<const uint4*>(&avh[row * KP + k0 + ldc8]));
            *reinterpret_cast<uint4*>(&Bs[row * LSTRIDE + ldc8]) =
                __ldg(reinterpret_cast<const uint4*>(&g_outWb[(long)(nblk0 + row) * KP + k0 + ldc8]));
        }
        __syncthreads();
#pragma unroll
        for (int ks = 0; ks < 4; ks++) {
            int koff = ks * 16;
            unsigned int a[4][4], b[4][2];
#pragma unroll
            for (int mi = 0; mi < 4; mi++) {
                int r = m0 + mi * 16 + (lane & 15);
                int ccol = koff + (lane >> 4) * 8;
                ldsm4(a[mi], as_base + (unsigned)(r * LSTRIDE + ccol) * 2u);
            }
#pragma unroll
            for (int ni = 0; ni < 4; ni++) {
                int r = n0w + ni * 8 + (lane & 7);
                int ccol = koff + ((lane >> 3) & 1) * 8;
                ldsm2(b[ni], bs_base + (unsigned)(r * LSTRIDE + ccol) * 2u);
            }
#pragma unroll
            for (int mi = 0; mi < 4; mi++)
#pragma unroll
                for (int ni = 0; ni < 4; ni++) mma16816(c[mi][ni], a[mi], b[ni]);
        }
    }
    __syncthreads();

    const int gid = lane >> 2;
    const int tig = lane & 3;
#pragma unroll
    for (int mi = 0; mi < 4; mi++) {
        int r0 = m0 + mi * 16 + gid;
        int r1 = r0 + 8;
        int t0 = stgt[r0], t1 = stgt[r1];
        float s0 = 0.f, s1 = 0.f;
#pragma unroll
        for (int ni = 0; ni < 4; ni++) {
            int n = nblk0 + n0w + ni * 8 + tig * 2;
            float b0 = out_b[n], b1 = out_b[n + 1];
            float l00 = c[mi][ni][0] + b0, l01 = c[mi][ni][1] + b1;
            float l10 = c[mi][ni][2] + b0, l11 = c[mi][ni][3] + b1;
            s0 += __expf(l00) + __expf(l01);
            s1 += __expf(l10) + __expf(l11);
            if (n == t0) g_tgtlogit[r0] = l00;
            if (n + 1 == t0) g_tgtlogit[r0] = l01;
            if (n == t1) g_tgtlogit[r1] = l10;
            if (n + 1 == t1) g_tgtlogit[r1] = l11;
        }
        s0 += __shfl_xor_sync(0xffffffffu, s0, 1);
        s0 += __shfl_xor_sync(0xffffffffu, s0, 2);
        s1 += __shfl_xor_sync(0xffffffffu, s1, 1);
        s1 += __shfl_xor_sync(0xffffffffu, s1, 2);
        if (tig == 0) { red[r0 * 4 + warp_n] = s0; red[r1 * 4 + warp_n] = s1; }
    }
    __syncthreads();
    if (tid < 128)
        g_part[tl * Bq + tid] = red[tid * 4] + red[tid * 4 + 1] + red[tid * 4 + 2] + red[tid * 4 + 3];
}

__device__ void combine_row(int b, int s, const int* trg_lens, float* red)
{
    int tid = threadIdx.x;
    float acc = 0.f;
    for (int i = tid; i < NTILES; i += 256) acc += __ldcg(&g_part[i * Bq + b]);
    red[tid] = acc;
    __syncthreads();
    for (int st = 128; st > 0; st >>= 1) {
        if (tid < st) red[tid] += red[tid + st];
        __syncthreads();
    }
    if (tid == 0) {
        float nll = logf(red[0]) - __ldcg(&g_tgtlogit[b]);
        g_nllbuf[s * Bq + b] = ((s + 1) < trg_lens[b]) ? -nll : 0.f;
    }
}

// ============================================================
// persistent encoder: 16 blocks, 64 steps x 2 layers
// ============================================================
__global__ __launch_bounds__(256) void enc_persist_k(const int* __restrict__ src_lens,
                                                     const float* __restrict__ enc_b1)
{
    __shared__ __align__(16) char raw[40960];
    __nv_bfloat16* As = (__nv_bfloat16*)raw;
    __nv_bfloat16* Bs = As + 128 * LSTRIDE;
    const int nbase = blockIdx.x * 32;
    float c[4][4][4];
    unsigned gen = 0;
    for (int t = 0; t < Lq; t++) {
        int p = t & 1;
        gates_mma(c, g_h1b[p], nullptr, 0, g_Whh0b, 512,
                  nullptr, nullptr, 0, nullptr, nullptr, 0, 1, nbase, As, Bs);
        cell_epi(c, nbase, g_G0 + (long)t * G4, (long)Lq * G4, nullptr, src_lens, t,
                 g_h1b[p], g_h1b[1 - p], g_c1, g_nh1b, nullptr, nullptr);
        gen++; gbar(&g_sync[0], 16u * gen);
        gates_mma(c, g_nh1b, nullptr, 0, g_Wih1b, 512,
                  g_h2b[p], g_Whh1b, 512, nullptr, nullptr, 0, 2, nbase, As, Bs);
        cell_epi(c, nbase, nullptr, 0, enc_b1, src_lens, t,
                 g_h2b[p], g_h2b[1 - p], g_c2, nullptr, g_S, nullptr);
        gen++; gbar(&g_sync[0], 16u * gen);
    }
}

// ============================================================
// persistent decoder: 148 blocks = 16 recurrent + 132 logits
// ============================================================
__global__ __launch_bounds__(256) void dec_persist_k(
    const int* __restrict__ trg_tokens, const int* __restrict__ trg_lens,
    const int* __restrict__ src_lens,
    const float* __restrict__ dec_b, const float* __restrict__ hid_b,
    const float* __restrict__ out_b)
{
    __shared__ __align__(16) char raw[40960];
    __nv_bfloat16* As = (__nv_bfloat16*)raw;
    __nv_bfloat16* Bs = As + 128 * LSTRIDE;
    const int blk = blockIdx.x;
    const int tid = threadIdx.x;

    if (blk < 16) {
        // ---- recurrent group ----
        float c[4][4][4];
        const int nbase = blk * 32;
        unsigned gen = 0;
        for (int s = 0; s < Tq - 1; s++) {
            int p = s & 1;
            gates_mma(c, g_trgEmbB, trg_tokens + s, Tq, g_dWihb, 1024,
                      g_avh[p], g_dWihb + 512, 1024,
                      g_dhb[p], g_dWhhb, 512, 3, nbase, As, Bs);
            cell_epi(c, nbase, nullptr, 0, dec_b, nullptr, 0,
                     g_dhb[p], g_dhb[1 - p], g_dc, nullptr, nullptr, g_dh);
            gen++; gbar(&g_sync[8], 16u * gen);

            attn8(blk * 8, src_lens, raw);
            gen++; gbar(&g_sync[8], 16u * gen);

            if (blk < 4) {
                if (s >= 2) wait_ge(&g_sync[32], (unsigned)(s - 1));
                hgemm_tile(c, g_dhb[(s + 1) & 1], g_hidWb, 1024,
                           g_ctxb, g_hidWb + 512, 1024, blk * 128, As, Bs);
                hid_epi(c, blk * 128, hid_b, g_avh[(s + 1) & 1]);
            }
            gen++; gbar(&g_sync[8], 16u * gen);
            if (blk == 0 && tid == 0) set_flag(&g_sync[24], (unsigned)(s + 1));
        }
    } else {
        // ---- logits group ----
        const int lb = blk - 16;
        int* stgt = (int*)(raw + 36864);
        float* red = (float*)(raw + 36864 + 512);
        unsigned gen = 0;
        for (int s = 0; s < Tq - 1; s++) {
            wait_ge(&g_sync[24], (unsigned)(s + 1));
            if (tid < 128) stgt[tid] = trg_tokens[tid * Tq + s + 1];
            __syncthreads();
            for (int w = 0; w < 2; w++) {
                int tl = lb + NLBLK * w;
                if (tl < NTILES)
                    logits_tile(tl, g_avh[(s + 1) & 1], out_b, stgt, red, As, Bs);
            }
            gen++; gbar(&g_sync[16], (unsigned)NLBLK * gen);
            if (lb < 128) combine_row(lb, s, trg_lens, red);
            gen++; gbar(&g_sync[16], (unsigned)NLBLK * gen);
            if (lb == 0 && tid == 0) set_flag(&g_sync[32], (unsigned)(s + 1));
        }
    }
}

// ============================================================
// standalone bf16 GEMM (G0 + decoder-init) — unchanged from R5
// ============================================================
__global__ __launch_bounds__(256) void hgemm_k(
    const __nv_bfloat16* __restrict__ A0, const int* __restrict__ map0, int ms0,
    const __nv_bfloat16* __restrict__ W0, int ldw0,
    const __nv_bfloat16* __restrict__ A1, const __nv_bfloat16* __restrict__ W1, int ldw1,
    int npairs,
    const float* __restrict__ bias, int N,
    float* __restrict__ outRaw, float* __restrict__ outTanhF,
    __nv_bfloat16* __restrict__ outBF)
{
    __shared__ __nv_bfloat16 As[128 * LSTRIDE];
    __shared__ __nv_bfloat16 Bs[128 * LSTRIDE];

    const int tid = threadIdx.x;
    const int lane = tid & 31;
    const int wid = tid >> 5;
    const int warp_n = wid & 3;
    const int m0 = (wid >> 2) * 64;
    const int mblk0 = blockIdx.x * 128;
    const int nblk0 = blockIdx.y * 128;

    float c[4][4][4];
#pragma unroll
    for (int mi = 0; mi < 4; mi++)
#pragma unroll
        for (int ni = 0; ni < 4; ni++)
#pragma unroll
            for (int q = 0; q < 4; q++) c[mi][ni][q] = 0.f;

    const unsigned as_base = (unsigned)__cvta_generic_to_shared(As);
    const unsigned bs_base = (unsigned)__cvta_generic_to_shared(Bs);
    const int ldrow = tid >> 3;
    const int ldc8 = (tid & 7) * 8;

    const __nv_bfloat16* Aps[2] = {A0, A1};
    const __nv_bfloat16* Wps[2] = {W0, W1};
    const int lws[2] = {ldw0, ldw1};

    for (int p = 0; p < npairs; p++) {
        const __nv_bfloat16* A = Aps[p];
        const __nv_bfloat16* W = Wps[p];
        const int ldw = lws[p];
        for (int kc = 0; kc < 8; kc++) {
            int k0 = kc * 64;
            __syncthreads();
#pragma unroll
            for (int q4 = 0; q4 < 4; q4++) {
                int row = q4 * 32 + ldrow;
                int gm = mblk0 + row;
                long arow = (p == 0 && map0) ? (long)map0[gm * ms0] * 512 : (long)gm * 512;
                *reinterpret_cast<uint4*>(&As[row * LSTRIDE + ldc8]) =
                    *reinterpret_cast<const uint4*>(&A[arow + k0 + ldc8]);
                *reinterpret_cast<uint4*>(&Bs[row * LSTRIDE + ldc8]) =
                    *reinterpret_cast<const uint4*>(&W[(long)(nblk0 + row) * ldw + k0 + ldc8]);
            }
            __syncthreads();
#pragma unroll
            for (int ks = 0; ks < 4; ks++) {
                int koff = ks * 16;
                unsigned int a[4][4], b[4][2];
#pragma unroll
                for (int mi = 0; mi < 4; mi++) {
                    int r = m0 + mi * 16 + (lane & 15);
                    int ccol = koff + (lane >> 4) * 8;
                    ldsm4(a[mi], as_base + (unsigned)(r * LSTRIDE + ccol) * 2u);
                }
#pragma unroll
                for (int ni = 0; ni < 4; ni++) {
                    int r = warp_n * 32 + ni * 8 + (lane & 7);
                    int ccol = koff + ((lane >> 3) & 1) * 8;
                    ldsm2(b[ni], bs_base + (unsigned)(r * LSTRIDE + ccol) * 2u);
                }
#pragma unroll
                for (int mi = 0; mi < 4; mi++)
#pragma unroll
                    for (int ni = 0; ni < 4; ni++) mma16816(c[mi][ni], a[mi], b[ni]);
            }
        }
    }

#pragma unroll
    for (int mi = 0; mi < 4; mi++)
#pragma unroll
        for (int ni = 0; ni < 4; ni++)
#pragma unroll
            for (int t2 = 0; t2 < 2; t2++) {
                int gm = mblk0 + m0 + mi * 16 + (lane >> 2) + 8 * t2;
#pragma unroll
                for (int u = 0; u < 2; u++) {
                    int n = nblk0 + warp_n * 32 + ni * 8 + 2 * (lane & 3) + u;
                    float v = c[mi][ni][2 * t2 + u];
                    if (bias) v += bias[n];
                    long oi = (long)gm * N + n;
                    if (outRaw) outRaw[oi] = v;
                    float tv = v;
                    if (outTanhF) { tv = tanhf(v); outTanhF[oi] = tv; }
                    if (outBF) outBF[oi] = __float2bfloat16_rn(outTanhF ? tv : v);
                }
            }
}

// ---------------- misc ----------------
__global__ void zero_k()
{
    int i = blockIdx.x * 256 + threadIdx.x;
    if (blockIdx.x == 0 && threadIdx.x < 64) g_sync[threadIdx.x] = 0u;
    if (i < HB) {
        g_h1b[0][i] = __float2bfloat16(0.f);
        g_h2b[0][i] = __float2bfloat16(0.f);
        g_avh[0][i] = __float2bfloat16(0.f);
        g_c1[i] = 0.f; g_c2[i] = 0.f;
    }
}

__global__ void f2bf_k(const float* __restrict__ in, __nv_bfloat16* __restrict__ out, int n)
{
    int i = blockIdx.x * 256 + threadIdx.x;
    if (i < n) out[i] = __float2bfloat16_rn(in[i]);
}

__global__ __launch_bounds__(256) void reduce_k(float* __restrict__ out)
{
    __shared__ float sm[256];
    float t = 0.f;
    for (int i = threadIdx.x; i < (Tq - 1) * Bq; i += 256) t += g_nllbuf[i];
    sm[threadIdx.x] = t;
    __syncthreads();
    for (int st = 128; st > 0; st >>= 1) {
        if (threadIdx.x < st) sm[threadIdx.x] += sm[threadIdx.x + st];
        __syncthreads();
    }
    if (threadIdx.x == 0) out[0] = sm[0];
}

// ---------------- launch ----------------
extern "C" void kernel_launch(void* const* d_in, const int* in_sizes, int n_in,
                              void* d_out, int out_size)
{
    const int*   src_tokens = (const int*)d_in[0];
    const int*   src_lens   = (const int*)d_in[1];
    const int*   trg_tokens = (const int*)d_in[2];
    const int*   trg_lens   = (const int*)d_in[3];
    const float* src_emb    = (const float*)d_in[4];
    const float* trg_emb    = (const float*)d_in[5];
    const float* enc_Wih0   = (const float*)d_in[6];
    const float* enc_Whh0   = (const float*)d_in[7];
    const float* enc_b0     = (const float*)d_in[8];
    const float* enc_Wih1   = (const float*)d_in[9];
    const float* enc_Whh1   = (const float*)d_in[10];
    const float* enc_b1     = (const float*)d_in[11];
    const float* dec_Wih    = (const float*)d_in[12];
    const float* dec_Whh    = (const float*)d_in[13];
    const float* dec_b      = (const float*)d_in[14];
    const float* hid_W      = (const float*)d_in[15];
    const float* hid_b      = (const float*)d_in[16];
    const float* out_W      = (const float*)d_in[17];
    const float* out_b      = (const float*)d_in[18];
    const float* init_W     = (const float*)d_in[19];
    const float* init_b     = (const float*)d_in[20];

    float *G0, *c1, *c2, *dc, *dh;
    __nv_bfloat16 *Wih0b, *Whh0b, *Wih1b, *Whh1b, *dWihb, *dWhhb, *hidWb, *initWb;
    __nv_bfloat16 *srcEmbB, *trgEmbB, *outWb, *c1b, *c2b, *dhb0;
    cudaGetSymbolAddress((void**)&G0, g_G0);
    cudaGetSymbolAddress((void**)&c1, g_c1);
    cudaGetSymbolAddress((void**)&c2, g_c2);
    cudaGetSymbolAddress((void**)&dc, g_dc);
    cudaGetSymbolAddress((void**)&dh, g_dh);
    cudaGetSymbolAddress((void**)&Wih0b, g_Wih0b);
    cudaGetSymbolAddress((void**)&Whh0b, g_Whh0b);
    cudaGetSymbolAddress((void**)&Wih1b, g_Wih1b);
    cudaGetSymbolAddress((void**)&Whh1b, g_Whh1b);
    cudaGetSymbolAddress((void**)&dWihb, g_dWihb);
    cudaGetSymbolAddress((void**)&dWhhb, g_dWhhb);
    cudaGetSymbolAddress((void**)&hidWb, g_hidWb);
    cudaGetSymbolAddress((void**)&initWb, g_initWb);
    cudaGetSymbolAddress((void**)&srcEmbB, g_srcEmbB);
    cudaGetSymbolAddress((void**)&trgEmbB, g_trgEmbB);
    cudaGetSymbolAddress((void**)&outWb, g_outWb);
    cudaGetSymbolAddress((void**)&c1b, g_c1b);
    cudaGetSymbolAddress((void**)&c2b, g_c2b);
    cudaGetSymbolAddress((void**)&dhb0, g_dhb);

    const int cb = (HB + 255) / 256;

    zero_k<<<cb, 256>>>();

    f2bf_k<<<(G4 * KP + 255) / 256, 256>>>(enc_Wih0, Wih0b, G4 * KP);
    f2bf_k<<<(G4 * KP + 255) / 256, 256>>>(enc_Whh0, Whh0b, G4 * KP);
    f2bf_k<<<(G4 * KP + 255) / 256, 256>>>(enc_Wih1, Wih1b, G4 * KP);
    f2bf_k<<<(G4 * KP + 255) / 256, 256>>>(enc_Whh1, Whh1b, G4 * KP);
    f2bf_k<<<(G4 * 1024 + 255) / 256, 256>>>(dec_Wih, dWihb, G4 * 1024);
    f2bf_k<<<(G4 * KP + 255) / 256, 256>>>(dec_Whh, dWhhb, G4 * KP);
    f2bf_k<<<(Hq * 1024 + 255) / 256, 256>>>(hid_W, hidWb, Hq * 1024);
    f2bf_k<<<(Hq * 1024 + 255) / 256, 256>>>(init_W, initWb, Hq * 1024);
    f2bf_k<<<(Vq * Eq + 255) / 256, 256>>>(src_emb, srcEmbB, Vq * Eq);
    f2bf_k<<<(Vq * Eq + 255) / 256, 256>>>(trg_emb, trgEmbB, Vq * Eq);
    f2bf_k<<<(Vq * KP + 255) / 256, 256>>>(out_W, outWb, Vq * KP);

    // G0 = emb(src) @ Wih0^T + b0
    hgemm_k<<<dim3(Bq * Lq / 128, G4 / 128), 256>>>(
        srcEmbB, src_tokens, 1, Wih0b, KP,
        nullptr, nullptr, 0, 1,
        enc_b0, G4, G0, nullptr, nullptr);

    // persistent encoder
    enc_persist_k<<<16, 256>>>(src_lens, enc_b1);

    // decoder init: c0 = [c1,c2] @ init_W^T + init_b ; h0 = tanh(c0)
    f2bf_k<<<cb, 256>>>(c1, c1b, HB);
    f2bf_k<<<cb, 256>>>(c2, c2b, HB);
    hgemm_k<<<dim3(1, Hq / 128), 256>>>(
        c1b, nullptr, 0, initWb, 1024,
        c2b, initWb + 512, 1024, 2,
        init_b, Hq, dc, dh, dhb0);

    // persistent decoder (16 recurrent blocks + 132 logits blocks)
    dec_persist_k<<<148, 256>>>(trg_tokens, trg_lens, src_lens, dec_b, hid_b, out_b);

    reduce_k<<<1, 256>>>((float*)d_out);
}

// round 8
// speedup vs baseline: 2.5649x; 2.5649x over previous
#include <cuda_runtime.h>
#include <cuda_bf16.h>
#include <math.h>
#include <stdint.h>

#define Bq 128
#define Lq 64
#define Tq 48
#define Eq 512
#define Hq 512
#define Vq 32000
#define G4 2048
#define KP 512
#define NTILES 250
#define LSTRIDE 72
#define HB (Bq * Hq)

// ---------------- fp32 scratch ----------------
__device__ float g_G0[Bq * Lq * G4];
__device__ float g_c1[HB], g_c2[HB];
__device__ float g_S[Bq * Lq * Hq];
__device__ float g_dh[HB], g_dc[HB];
__device__ float g_nllbuf[(Tq - 1) * Bq];
__device__ float g_part[NTILES * Bq];
__device__ float g_tgtlogit[Bq];

// ---------------- bf16 weights ----------------
__device__ __nv_bfloat16 g_Wih0b[G4 * KP], g_Whh0b[G4 * KP];
__device__ __nv_bfloat16 g_Wih1b[G4 * KP], g_Whh1b[G4 * KP];
__device__ __nv_bfloat16 g_dWihb[G4 * 1024], g_dWhhb[G4 * KP];
__device__ __nv_bfloat16 g_hidWb[Hq * 1024], g_initWb[Hq * 1024];
__device__ __nv_bfloat16 g_srcEmbB[Vq * Eq], g_trgEmbB[Vq * Eq];
__device__ __nv_bfloat16 g_outWb[Vq * KP];

// ---------------- bf16 states ----------------
__device__ __nv_bfloat16 g_h1b[2][HB], g_h2b[2][HB], g_dhb[2][HB];
__device__ __nv_bfloat16 g_nh1b[HB];
__device__ __nv_bfloat16 g_c1b[HB], g_c2b[HB];
__device__ __nv_bfloat16 g_ctxb[HB];
__device__ __nv_bfloat16 g_avh[2][HB];

// ---------------- MMA helpers ----------------
__device__ __forceinline__ void ldsm4(unsigned* r, unsigned addr) {
    asm volatile("ldmatrix.sync.aligned.m8n8.x4.shared.b16 {%0,%1,%2,%3}, [%4];"
                 : "=r"(r[0]), "=r"(r[1]), "=r"(r[2]), "=r"(r[3]) : "r"(addr));
}
__device__ __forceinline__ void ldsm2(unsigned* r, unsigned addr) {
    asm volatile("ldmatrix.sync.aligned.m8n8.x2.shared.b16 {%0,%1}, [%2];"
                 : "=r"(r[0]), "=r"(r[1]) : "r"(addr));
}
__device__ __forceinline__ void mma16816(float* c, const unsigned* a, const unsigned* b) {
    asm volatile("mma.sync.aligned.m16n8k16.row.col.f32.bf16.bf16.f32 "
                 "{%0,%1,%2,%3}, {%4,%5,%6,%7}, {%8,%9}, {%0,%1,%2,%3};"
                 : "+f"(c[0]), "+f"(c[1]), "+f"(c[2]), "+f"(c[3])
                 : "r"(a[0]), "r"(a[1]), "r"(a[2]), "r"(a[3]), "r"(b[0]), "r"(b[1]));
}

__device__ __forceinline__ float sigm_f(float x) { return __fdividef(1.f, 1.f + __expf(-x)); }
__device__ __forceinline__ float tanh_f(float x) { return __fdividef(2.f, 1.f + __expf(-2.f * x)) - 1.f; }

// ============================================================
// gates GEMM (pipelined) + fused LSTM cell.  M=128, block owns
// 32 cols of EACH of the 4 gates; fragment ni = gate.
// ============================================================
__device__ void gates_body(
    int nbase,
    const __nv_bfloat16* A0, const int* map0, int ms0, const __nv_bfloat16* W0, int ldw0,
    const __nv_bfloat16* A1, const __nv_bfloat16* W1, int ldw1,
    const __nv_bfloat16* A2, const __nv_bfloat16* W2, int ldw2,
    int npairs,
    const float* initp, long initStride, const float* bias,
    const int* lens, int t,
    const __nv_bfloat16* hin, __nv_bfloat16* hout, float* cf,
    __nv_bfloat16* nh_out, float* S_out, float* hf_out,
    __nv_bfloat16* As, __nv_bfloat16* Bs)
{
    const int tid = threadIdx.x, lane = tid & 31, wid = tid >> 5;
    const int m0 = (wid >> 2) * 64, warp_n = wid & 3;
    const unsigned as_base = (unsigned)__cvta_generic_to_shared(As);
    const unsigned bs_base = (unsigned)__cvta_generic_to_shared(Bs);
    const int ldrow = tid >> 3, ldc8 = (tid & 7) * 8;

    float c[4][4][4];
#pragma unroll
    for (int mi = 0; mi < 4; mi++)
#pragma unroll
        for (int ni = 0; ni < 4; ni++)
#pragma unroll
            for (int q = 0; q < 4; q++) c[mi][ni][q] = 0.f;

    uint4 ra[4], rb[4];
    const int total = npairs * 8;
    auto fetch = [&](int ch) {
        int p = ch >> 3, k0 = (ch & 7) * 64;
        const __nv_bfloat16* A = (p == 0) ? A0 : ((p == 1) ? A1 : A2);
        const __nv_bfloat16* W = (p == 0) ? W0 : ((p == 1) ? W1 : W2);
        int ldw = (p == 0) ? ldw0 : ((p == 1) ? ldw1 : ldw2);
#pragma unroll
        for (int q = 0; q < 4; q++) {
            int row = q * 32 + ldrow;
            long arow = (p == 0 && map0) ? (long)map0[row * ms0] * 512 : (long)row * 512;
            ra[q] = *reinterpret_cast<const uint4*>(&A[arow + k0 + ldc8]);
            int wrow = ((row >> 5) * 512) + nbase + (row & 31);
            rb[q] = *reinterpret_cast<const uint4*>(&W[(long)wrow * ldw + k0 + ldc8]);
        }
    };
    fetch(0);
    for (int ch = 0; ch < total; ch++) {
        __syncthreads();
#pragma unroll
        for (int q = 0; q < 4; q++) {
            int row = q * 32 + ldrow;
            *reinterpret_cast<uint4*>(&As[row * LSTRIDE + ldc8]) = ra[q];
            *reinterpret_cast<uint4*>(&Bs[row * LSTRIDE + ldc8]) = rb[q];
        }
        __syncthreads();
        if (ch + 1 < total) fetch(ch + 1);
#pragma unroll
        for (int ks = 0; ks < 4; ks++) {
            int koff = ks * 16;
            unsigned a[4][4], b[4][2];
#pragma unroll
            for (int mi = 0; mi < 4; mi++) {
                int r = m0 + mi * 16 + (lane & 15);
                int ccol = koff + (lane >> 4) * 8;
                ldsm4(a[mi], as_base + (unsigned)(r * LSTRIDE + ccol) * 2u);
            }
#pragma unroll
            for (int ni = 0; ni < 4; ni++) {
                int r = ni * 32 + warp_n * 8 + (lane & 7);
                int ccol = koff + ((lane >> 3) & 1) * 8;
                ldsm2(b[ni], bs_base + (unsigned)(r * LSTRIDE + ccol) * 2u);
            }
#pragma unroll
            for (int mi = 0; mi < 4; mi++)
#pragma unroll
                for (int ni = 0; ni < 4; ni++) mma16816(c[mi][ni], a[mi], b[ni]);
        }
    }

    // cell epilogue
#pragma unroll
    for (int mi = 0; mi < 4; mi++) {
#pragma unroll
        for (int t2 = 0; t2 < 2; t2++) {
            int row = m0 + mi * 16 + (lane >> 2) + 8 * t2;
#pragma unroll
            for (int u = 0; u < 2; u++) {
                int j = nbase + warp_n * 8 + 2 * (lane & 3) + u;
                int e = 2 * t2 + u;
                float gi = c[mi][0][e], gf = c[mi][1][e], gg = c[mi][2][e], go = c[mi][3][e];
                if (initp) {
                    const float* ip = initp + (long)row * initStride;
                    gi += ip[j]; gf += ip[512 + j]; gg += ip[1024 + j]; go += ip[1536 + j];
                }
                if (bias) {
                    gi += bias[j]; gf += bias[512 + j]; gg += bias[1024 + j]; go += bias[1536 + j];
                }
                float i_ = sigm_f(gi), f_ = sigm_f(gf), tg = tanh_f(gg), o_ = sigm_f(go);
                int idx = row * 512 + j;
                float cn = f_ * cf[idx] + i_ * tg;
                float hn = o_ * tanh_f(cn);
                bool mk = lens ? (t < lens[row]) : true;
                if (nh_out) nh_out[idx] = __float2bfloat16_rn(hn);
                if (S_out) S_out[(long)row * Lq * 512 + (long)t * 512 + j] = mk ? hn : 0.f;
                if (hf_out) hf_out[idx] = hn;
                if (mk) { cf[idx] = cn; hout[idx] = __float2bfloat16_rn(hn); }
                else hout[idx] = hin[idx];
            }
        }
    }
}

// ============================================================
// logits tile (pipelined) + exp-sum / target epilogue
// ============================================================
__device__ void logits_body(
    int tl, int ls, const __nv_bfloat16* avh, const float* out_b,
    const int* trg_tokens, __nv_bfloat16* As, __nv_bfloat16* Bs,
    int* stgt, float* red)
{
    const int tid = threadIdx.x, lane = tid & 31, wid = tid >> 5;
    const int m0 = (wid >> 2) * 64, warp_n = wid & 3;
    const int n0w = warp_n * 32;
    const int nblk0 = tl * 128;
    if (tid < 128) stgt[tid] = trg_tokens[tid * Tq + ls + 1];

    float c[4][4][4];
#pragma unroll
    for (int mi = 0; mi < 4; mi++)
#pragma unroll
        for (int ni = 0; ni < 4; ni++)
#pragma unroll
            for (int q = 0; q < 4; q++) c[mi][ni][q] = 0.f;

    const unsigned as_base = (unsigned)__cvta_generic_to_shared(As);
    const unsigned bs_base = (unsigned)__cvta_generic_to_shared(Bs);
    const int ldrow = tid >> 3, ldc8 = (tid & 7) * 8;

    uint4 ra[4], rb[4];
    auto fetch = [&](int kc) {
        int k0 = kc * 64;
#pragma unroll
        for (int q = 0; q < 4; q++) {
            int row = q * 32 + ldrow;
            ra[q] = *reinterpret_cast<const uint4*>(&avh[row * KP + k0 + ldc8]);
            rb[q] = *reinterpret_cast<const uint4*>(&g_outWb[(long)(nblk0 + row) * KP + k0 + ldc8]);
        }
    };
    fetch(0);
    for (int kc = 0; kc < 8; kc++) {
        __syncthreads();
#pragma unroll
        for (int q = 0; q < 4; q++) {
            int row = q * 32 + ldrow;
            *reinterpret_cast<uint4*>(&As[row * LSTRIDE + ldc8]) = ra[q];
            *reinterpret_cast<uint4*>(&Bs[row * LSTRIDE + ldc8]) = rb[q];
        }
        __syncthreads();
        if (kc + 1 < 8) fetch(kc + 1);
#pragma unroll
        for (int ks = 0; ks < 4; ks++) {
            int koff = ks * 16;
            unsigned a[4][4], b[4][2];
#pragma unroll
            for (int mi = 0; mi < 4; mi++) {
                int r = m0 + mi * 16 + (lane & 15);
                int ccol = koff + (lane >> 4) * 8;
                ldsm4(a[mi], as_base + (unsigned)(r * LSTRIDE + ccol) * 2u);
            }
#pragma unroll
            for (int ni = 0; ni < 4; ni++) {
                int r = n0w + ni * 8 + (lane & 7);
                int ccol = koff + ((lane >> 3) & 1) * 8;
                ldsm2(b[ni], bs_base + (unsigned)(r * LSTRIDE + ccol) * 2u);
            }
#pragma unroll
            for (int mi = 0; mi < 4; mi++)
#pragma unroll
                for (int ni = 0; ni < 4; ni++) mma16816(c[mi][ni], a[mi], b[ni]);
        }
    }
    __syncthreads();

    const int gid = lane >> 2, tig = lane & 3;
#pragma unroll
    for (int mi = 0; mi < 4; mi++) {
        int r0 = m0 + mi * 16 + gid;
        int r1 = r0 + 8;
        int t0 = stgt[r0], t1 = stgt[r1];
        float s0 = 0.f, s1 = 0.f;
#pragma unroll
        for (int ni = 0; ni < 4; ni++) {
            int n = nblk0 + n0w + ni * 8 + tig * 2;
            float b0 = out_b[n], b1 = out_b[n + 1];
            float l00 = c[mi][ni][0] + b0, l01 = c[mi][ni][1] + b1;
            float l10 = c[mi][ni][2] + b0, l11 = c[mi][ni][3] + b1;
            s0 += __expf(l00) + __expf(l01);
            s1 += __expf(l10) + __expf(l11);
            if (n == t0) g_tgtlogit[r0] = l00;
            if (n + 1 == t0) g_tgtlogit[r0] = l01;
            if (n == t1) g_tgtlogit[r1] = l10;
            if (n + 1 == t1) g_tgtlogit[r1] = l11;
        }
        s0 += __shfl_xor_sync(0xffffffffu, s0, 1);
        s0 += __shfl_xor_sync(0xffffffffu, s0, 2);
        s1 += __shfl_xor_sync(0xffffffffu, s1, 1);
        s1 += __shfl_xor_sync(0xffffffffu, s1, 2);
        if (tig == 0) { red[r0 * 4 + warp_n] = s0; red[r1 * 4 + warp_n] = s1; }
    }
    __syncthreads();
    if (tid < 128)
        g_part[tl * Bq + tid] = red[tid * 4] + red[tid * 4 + 1] + red[tid * 4 + 2] + red[tid * 4 + 3];
}

// ============================================================
// encoder wavefront: blocks 0-15 layer0(t0), blocks 16-31 layer1(t1)
// ============================================================
__global__ __launch_bounds__(256) void enc_wave_k(
    int t0, int t1, const int* __restrict__ src_lens, const float* __restrict__ enc_b1)
{
    __shared__ __nv_bfloat16 As[128 * LSTRIDE];
    __shared__ __nv_bfloat16 Bs[128 * LSTRIDE];
    const int nbase = (blockIdx.x & 15) * 32;
    if (blockIdx.x < 16) {
        if (t0 < 0) return;
        int p = t0 & 1;
        gates_body(nbase, g_h1b[p], nullptr, 0, g_Whh0b, 512,
                   nullptr, nullptr, 0, nullptr, nullptr, 0, 1,
                   g_G0 + (long)t0 * G4, (long)Lq * G4, nullptr, src_lens, t0,
                   g_h1b[p], g_h1b[1 - p], g_c1, g_nh1b, nullptr, nullptr, As, Bs);
    } else {
        if (t1 < 0) return;
        int p = t1 & 1;
        gates_body(nbase, g_nh1b, nullptr, 0, g_Wih1b, 512,
                   g_h2b[p], g_Whh1b, 512, nullptr, nullptr, 0, 2,
                   nullptr, 0, enc_b1, src_lens, t1,
                   g_h2b[p], g_h2b[1 - p], g_c2, nullptr, g_S, nullptr, As, Bs);
    }
}

// ============================================================
// decoder main: blocks 0-15 gates(s), blocks 16-265 logits(s-1)
// ============================================================
__global__ __launch_bounds__(256) void dec_main_k(
    int s, const int* __restrict__ trg_tokens,
    const float* __restrict__ dec_b, const float* __restrict__ out_b)
{
    __shared__ __nv_bfloat16 As[128 * LSTRIDE];
    __shared__ __nv_bfloat16 Bs[128 * LSTRIDE];
    __shared__ int stgt[128];
    __shared__ float red[512];
    if (blockIdx.x < 16) {
        if (s > Tq - 2) return;
        int p = s & 1;
        gates_body(blockIdx.x * 32, g_trgEmbB, trg_tokens + s, Tq, g_dWihb, 1024,
                   g_avh[p], g_dWihb + 512, 1024,
                   g_dhb[p], g_dWhhb, 512, 3,
                   nullptr, 0, dec_b, nullptr, 0,
                   g_dhb[p], g_dhb[1 - p], g_dc, nullptr, nullptr, g_dh, As, Bs);
    } else {
        int ls = s - 1;
        if (ls < 0) return;
        logits_body(blockIdx.x - 16, ls, g_avh[s & 1], out_b, trg_tokens, As, Bs, stgt, red);
    }
}

// ============================================================
// attention (blocks 0-127, row = blk) + NLL combine(s-1) (block 128)
// ============================================================
__global__ __launch_bounds__(256) void attn_combine_k(
    int s, const int* __restrict__ src_lens, const int* __restrict__ trg_lens)
{
    __shared__ float sh[512];
    __shared__ float part[256];
    __shared__ float sc[64];
    __shared__ float sinv;
    int tid = threadIdx.x;
    if (blockIdx.x < 128) {
        if (s > Tq - 2) return;
        int b = blockIdx.x;
        sh[tid] = g_dh[(long)b * Hq + tid];
        sh[tid + 256] = g_dh[(long)b * Hq + tid + 256];
        __syncthreads();
        int l = tid >> 2, q = tid & 3;
        const float* Sb = g_S + (long)b * Lq * Hq + (long)l * Hq + q * 128;
        float pv = 0.f;
#pragma unroll 8
        for (int k = 0; k < 128; k++) pv = fmaf(sh[q * 128 + k], Sb[k], pv);
        part[l * 4 + q] = pv;
        __syncthreads();
        if (tid < Lq) {
            float sv = part[tid * 4] + part[tid * 4 + 1] + part[tid * 4 + 2] + part[tid * 4 + 3];
            if (tid >= src_lens[b]) sv = -1e9f;
            sc[tid] = __expf(sv);
        }
        __syncthreads();
        if (tid == 0) {
            float ts = 0.f;
            for (int i = 0; i < Lq; i++) ts += sc[i];
            sinv = 1.f / ts;
        }
        __syncthreads();
        if (tid < Lq) sc[tid] *= sinv;
        __syncthreads();
        for (int j = tid; j < Hq; j += 256) {
            const float* Sb2 = g_S + (long)b * Lq * Hq + j;
            float acc = 0.f;
#pragma unroll 8
            for (int l2 = 0; l2 < Lq; l2++) acc = fmaf(sc[l2], Sb2[(long)l2 * Hq], acc);
            g_ctxb[(long)b * Hq + j] = __float2bfloat16_rn(acc);
        }
    } else {
        int ls = s - 1;
        if (ls < 0) return;
        int b = tid;
        if (b < 128) {
            float tot = 0.f;
            for (int i = 0; i < NTILES; i++) tot += g_part[i * Bq + b];
            float nll = logf(tot) - g_tgtlogit[b];
            g_nllbuf[ls * Bq + b] = ((ls + 1) < trg_lens[b]) ? -nll : 0.f;
        }
    }
}

// ============================================================
// standalone bf16 GEMM (G0, decoder-init, hid) — pipelined
// ============================================================
__global__ __launch_bounds__(256) void hgemm_k(
    const __nv_bfloat16* __restrict__ A0, const int* __restrict__ map0, int ms0,
    const __nv_bfloat16* __restrict__ W0, int ldw0,
    const __nv_bfloat16* __restrict__ A1, const __nv_bfloat16* __restrict__ W1, int ldw1,
    int npairs,
    const float* __restrict__ bias, int N,
    float* __restrict__ outRaw, float* __restrict__ outTanhF,
    __nv_bfloat16* __restrict__ outBF)
{
    __shared__ __nv_bfloat16 As[128 * LSTRIDE];
    __shared__ __nv_bfloat16 Bs[128 * LSTRIDE];
    const int tid = threadIdx.x, lane = tid & 31, wid = tid >> 5;
    const int m0 = (wid >> 2) * 64, warp_n = wid & 3;
    const int mblk0 = blockIdx.x * 128, nblk0 = blockIdx.y * 128;

    float c[4][4][4];
#pragma unroll
    for (int mi = 0; mi < 4; mi++)
#pragma unroll
        for (int ni = 0; ni < 4; ni++)
#pragma unroll
            for (int q = 0; q < 4; q++) c[mi][ni][q] = 0.f;

    const unsigned as_base = (unsigned)__cvta_generic_to_shared(As);
    const unsigned bs_base = (unsigned)__cvta_generic_to_shared(Bs);
    const int ldrow = tid >> 3, ldc8 = (tid & 7) * 8;

    uint4 ra[4], rb[4];
    const int total = npairs * 8;
    auto fetch = [&](int ch) {
        int p = ch >> 3, k0 = (ch & 7) * 64;
        const __nv_bfloat16* A = (p == 0) ? A0 : A1;
        const __nv_bfloat16* W = (p == 0) ? W0 : W1;
        int ldw = (p == 0) ? ldw0 : ldw1;
#pragma unroll
        for (int q = 0; q < 4; q++) {
            int row = q * 32 + ldrow;
            int gm = mblk0 + row;
            long arow = (p == 0 && map0) ? (long)map0[gm * ms0] * 512 : (long)gm * 512;
            ra[q] = *reinterpret_cast<const uint4*>(&A[arow + k0 + ldc8]);
            rb[q] = *reinterpret_cast<const uint4*>(&W[(long)(nblk0 + row) * ldw + k0 + ldc8]);
        }
    };
    fetch(0);
    for (int ch = 0; ch < total; ch++) {
        __syncthreads();
#pragma unroll
        for (int q = 0; q < 4; q++) {
            int row = q * 32 + ldrow;
            *reinterpret_cast<uint4*>(&As[row * LSTRIDE + ldc8]) = ra[q];
            *reinterpret_cast<uint4*>(&Bs[row * LSTRIDE + ldc8]) = rb[q];
        }
        __syncthreads();
        if (ch + 1 < total) fetch(ch + 1);
#pragma unroll
        for (int ks = 0; ks < 4; ks++) {
            int koff = ks * 16;
            unsigned a[4][4], b[4][2];
#pragma unroll
            for (int mi = 0; mi < 4; mi++) {
                int r = m0 + mi * 16 + (lane & 15);
                int ccol = koff + (lane >> 4) * 8;
                ldsm4(a[mi], as_base + (unsigned)(r * LSTRIDE + ccol) * 2u);
            }
#pragma unroll
            for (int ni = 0; ni < 4; ni++) {
                int r = warp_n * 32 + ni * 8 + (lane & 7);
                int ccol = koff + ((lane >> 3) & 1) * 8;
                ldsm2(b[ni], bs_base + (unsigned)(r * LSTRIDE + ccol) * 2u);
            }
#pragma unroll
            for (int mi = 0; mi < 4; mi++)
#pragma unroll
                for (int ni = 0; ni < 4; ni++) mma16816(c[mi][ni], a[mi], b[ni]);
        }
    }

#pragma unroll
    for (int mi = 0; mi < 4; mi++)
#pragma unroll
        for (int ni = 0; ni < 4; ni++)
#pragma unroll
            for (int t2 = 0; t2 < 2; t2++) {
                int gm = mblk0 + m0 + mi * 16 + (lane >> 2) + 8 * t2;
#pragma unroll
                for (int u = 0; u < 2; u++) {
                    int n = nblk0 + warp_n * 32 + ni * 8 + 2 * (lane & 3) + u;
                    float v = c[mi][ni][2 * t2 + u];
                    if (bias) v += bias[n];
                    long oi = (long)gm * N + n;
                    if (outRaw) outRaw[oi] = v;
                    float tv = v;
                    if (outTanhF) { tv = tanhf(v); outTanhF[oi] = tv; }
                    if (outBF) outBF[oi] = __float2bfloat16_rn(outTanhF ? tv : v);
                }
            }
}

// ---------------- misc ----------------
__global__ void zero_k()
{
    int i = blockIdx.x * 256 + threadIdx.x;
    if (i < HB) {
        g_h1b[0][i] = __float2bfloat16(0.f);
        g_h2b[0][i] = __float2bfloat16(0.f);
        g_avh[0][i] = __float2bfloat16(0.f);
        g_c1[i] = 0.f; g_c2[i] = 0.f;
    }
}

__global__ void f2bf_k(const float* __restrict__ in, __nv_bfloat16* __restrict__ out, int n)
{
    int i = blockIdx.x * 256 + threadIdx.x;
    if (i < n) out[i] = __float2bfloat16_rn(in[i]);
}

__global__ __launch_bounds__(256) void reduce_k(float* __restrict__ out)
{
    __shared__ float sm[256];
    float t = 0.f;
    for (int i = threadIdx.x; i < (Tq - 1) * Bq; i += 256) t += g_nllbuf[i];
    sm[threadIdx.x] = t;
    __syncthreads();
    for (int st = 128; st > 0; st >>= 1) {
        if (threadIdx.x < st) sm[threadIdx.x] += sm[threadIdx.x + st];
        __syncthreads();
    }
    if (threadIdx.x == 0) out[0] = sm[0];
}

// ---------------- launch ----------------
extern "C" void kernel_launch(void* const* d_in, const int* in_sizes, int n_in,
                              void* d_out, int out_size)
{
    const int*   src_tokens = (const int*)d_in[0];
    const int*   src_lens   = (const int*)d_in[1];
    const int*   trg_tokens = (const int*)d_in[2];
    const int*   trg_lens   = (const int*)d_in[3];
    const float* src_emb    = (const float*)d_in[4];
    const float* trg_emb    = (const float*)d_in[5];
    const float* enc_Wih0   = (const float*)d_in[6];
    const float* enc_Whh0   = (const float*)d_in[7];
    const float* enc_b0     = (const float*)d_in[8];
    const float* enc_Wih1   = (const float*)d_in[9];
    const float* enc_Whh1   = (const float*)d_in[10];
    const float* enc_b1     = (const float*)d_in[11];
    const float* dec_Wih    = (const float*)d_in[12];
    const float* dec_Whh    = (const float*)d_in[13];
    const float* dec_b      = (const float*)d_in[14];
    const float* hid_W      = (const float*)d_in[15];
    const float* hid_b      = (const float*)d_in[16];
    const float* out_W      = (const float*)d_in[17];
    const float* out_b      = (const float*)d_in[18];
    const float* init_W     = (const float*)d_in[19];
    const float* init_b     = (const float*)d_in[20];

    float *G0, *c1, *c2, *dc, *dh;
    __nv_bfloat16 *Wih0b, *Whh0b, *Wih1b, *Whh1b, *dWihb, *dWhhb, *hidWb, *initWb;
    __nv_bfloat16 *srcEmbB, *trgEmbB, *outWb, *c1b, *c2b, *dhb0, *ctxb, *avh0;
    cudaGetSymbolAddress((void**)&G0, g_G0);
    cudaGetSymbolAddress((void**)&c1, g_c1);
    cudaGetSymbolAddress((void**)&c2, g_c2);
    cudaGetSymbolAddress((void**)&dc, g_dc);
    cudaGetSymbolAddress((void**)&dh, g_dh);
    cudaGetSymbolAddress((void**)&Wih0b, g_Wih0b);
    cudaGetSymbolAddress((void**)&Whh0b, g_Whh0b);
    cudaGetSymbolAddress((void**)&Wih1b, g_Wih1b);
    cudaGetSymbolAddress((void**)&Whh1b, g_Whh1b);
    cudaGetSymbolAddress((void**)&dWihb, g_dWihb);
    cudaGetSymbolAddress((void**)&dWhhb, g_dWhhb);
    cudaGetSymbolAddress((void**)&hidWb, g_hidWb);
    cudaGetSymbolAddress((void**)&initWb, g_initWb);
    cudaGetSymbolAddress((void**)&srcEmbB, g_srcEmbB);
    cudaGetSymbolAddress((void**)&trgEmbB, g_trgEmbB);
    cudaGetSymbolAddress((void**)&outWb, g_outWb);
    cudaGetSymbolAddress((void**)&c1b, g_c1b);
    cudaGetSymbolAddress((void**)&c2b, g_c2b);
    cudaGetSymbolAddress((void**)&dhb0, g_dhb);
    cudaGetSymbolAddress((void**)&ctxb, g_ctxb);
    cudaGetSymbolAddress((void**)&avh0, g_avh);
    __nv_bfloat16* dhb[2] = {dhb0, dhb0 + HB};
    __nv_bfloat16* avh[2] = {avh0, avh0 + HB};

    const int cb = (HB + 255) / 256;

    zero_k<<<cb, 256>>>();

    f2bf_k<<<(G4 * KP + 255) / 256, 256>>>(enc_Wih0, Wih0b, G4 * KP);
    f2bf_k<<<(G4 * KP + 255) / 256, 256>>>(enc_Whh0, Whh0b, G4 * KP);
    f2bf_k<<<(G4 * KP + 255) / 256, 256>>>(enc_Wih1, Wih1b, G4 * KP);
    f2bf_k<<<(G4 * KP + 255) / 256, 256>>>(enc_Whh1, Whh1b, G4 * KP);
    f2bf_k<<<(G4 * 1024 + 255) / 256, 256>>>(dec_Wih, dWihb, G4 * 1024);
    f2bf_k<<<(G4 * KP + 255) / 256, 256>>>(dec_Whh, dWhhb, G4 * KP);
    f2bf_k<<<(Hq * 1024 + 255) / 256, 256>>>(hid_W, hidWb, Hq * 1024);
    f2bf_k<<<(Hq * 1024 + 255) / 256, 256>>>(init_W, initWb, Hq * 1024);
    f2bf_k<<<(Vq * Eq + 255) / 256, 256>>>(src_emb, srcEmbB, Vq * Eq);
    f2bf_k<<<(Vq * Eq + 255) / 256, 256>>>(trg_emb, trgEmbB, Vq * Eq);
    f2bf_k<<<(Vq * KP + 255) / 256, 256>>>(out_W, outWb, Vq * KP);

    // G0 = emb(src) @ Wih0^T + b0
    hgemm_k<<<dim3(Bq * Lq / 128, G4 / 128), 256>>>(
        srcEmbB, src_tokens, 1, Wih0b, KP,
        nullptr, nullptr, 0, 1,
        enc_b0, G4, G0, nullptr, nullptr);

    // ---------------- encoder (wavefront: layer0(t) || layer1(t-1)) ----------------
    for (int t = 0; t <= Lq; t++)
        enc_wave_k<<<32, 256>>>(t < Lq ? t : -1, t - 1, src_lens, enc_b1);

    // decoder init: c0 = [c1,c2] @ init_W^T + init_b ; h0 = tanh(c0)
    f2bf_k<<<cb, 256>>>(c1, c1b, HB);
    f2bf_k<<<cb, 256>>>(c2, c2b, HB);
    hgemm_k<<<dim3(1, Hq / 128), 256>>>(
        c1b, nullptr, 0, initWb, 1024,
        c2b, initWb + 512, 1024, 2,
        init_b, Hq, dc, dh, dhb[0]);

    // ---------------- decoder (gates(s) || logits(s-1); combine rides attn) ----------------
    for (int s = 0; s < Tq - 1; s++) {
        dec_main_k<<<16 + NTILES, 256>>>(s, trg_tokens, dec_b, out_b);
        attn_combine_k<<<129, 256>>>(s, src_lens, trg_lens);
        hgemm_k<<<dim3(1, Hq / 128), 256>>>(
            dhb[(s + 1) & 1], nullptr, 0, hidWb, 1024,
            ctxb, hidWb + 512, 1024, 2,
            hid_b, Hq, nullptr, nullptr, avh[(s + 1) & 1]);
    }
    // tail: logits(T-2) + combine(T-2)
    dec_main_k<<<16 + NTILES, 256>>>(Tq - 1, trg_tokens, dec_b, out_b);
    attn_combine_k<<<129, 256>>>(Tq - 1, src_lens, trg_lens);

    reduce_k<<<1, 256>>>((float*)d_out);
}

// round 9
// speedup vs baseline: 2.7043x; 1.0543x over previous
#include <cuda_runtime.h>
#include <cuda_bf16.h>
#include <math.h>
#include <stdint.h>

#define Bq 128
#define Lq 64
#define Tq 48
#define Eq 512
#define Hq 512
#define Vq 32000
#define G4 2048
#define KP 512
#define NTILES 250
#define LSTRIDE 72
#define HB (Bq * Hq)

// ---------------- fp32 scratch ----------------
__device__ float g_G0[Bq * Lq * G4];              // encoder layer0 input gates
__device__ float g_GV[(Tq - 1) * Bq * G4];        // decoder v@dWih_left + dec_b, all steps
__device__ float g_c1[HB], g_c2[HB];
__device__ float g_S[Bq * Lq * Hq];
__device__ float g_dh[HB], g_dc[HB];
__device__ float g_avf[HB];                       // hid h-part (fp32)
__device__ float g_nllbuf[(Tq - 1) * Bq];
__device__ float g_part[NTILES * Bq];
__device__ float g_tgtlogit[Bq];

// ---------------- bf16 weights ----------------
__device__ __nv_bfloat16 g_Wih0b[G4 * KP], g_Whh0b[G4 * KP];
__device__ __nv_bfloat16 g_Wih1b[G4 * KP], g_Whh1b[G4 * KP];
__device__ __nv_bfloat16 g_dWihb[G4 * 1024], g_dWhhb[G4 * KP];
__device__ __nv_bfloat16 g_hidWb[Hq * 1024], g_initWb[Hq * 1024];
__device__ __nv_bfloat16 g_outWb[Vq * KP];

// ---------------- compact gathered embeddings (bf16) ----------------
__device__ __nv_bfloat16 g_xsB[Bq * Lq * Eq];     // src emb rows, m = b*L+t
__device__ __nv_bfloat16 g_vembB[(Tq - 1) * Bq * Eq]; // trg emb rows, m = s*128+b

// ---------------- bf16 states ----------------
__device__ __nv_bfloat16 g_h1b[2][HB], g_h2b[2][HB], g_dhb[2][HB];
__device__ __nv_bfloat16 g_nh1b[HB];
__device__ __nv_bfloat16 g_c1b[HB], g_c2b[HB];
__device__ __nv_bfloat16 g_ctxb[HB];
__device__ __nv_bfloat16 g_avh[2][HB];

// ---------------- MMA helpers ----------------
__device__ __forceinline__ void ldsm4(unsigned* r, unsigned addr) {
    asm volatile("ldmatrix.sync.aligned.m8n8.x4.shared.b16 {%0,%1,%2,%3}, [%4];"
                 : "=r"(r[0]), "=r"(r[1]), "=r"(r[2]), "=r"(r[3]) : "r"(addr));
}
__device__ __forceinline__ void ldsm2(unsigned* r, unsigned addr) {
    asm volatile("ldmatrix.sync.aligned.m8n8.x2.shared.b16 {%0,%1}, [%2];"
                 : "=r"(r[0]), "=r"(r[1]) : "r"(addr));
}
__device__ __forceinline__ void mma16816(float* c, const unsigned* a, const unsigned* b) {
    asm volatile("mma.sync.aligned.m16n8k16.row.col.f32.bf16.bf16.f32 "
                 "{%0,%1,%2,%3}, {%4,%5,%6,%7}, {%8,%9}, {%0,%1,%2,%3};"
                 : "+f"(c[0]), "+f"(c[1]), "+f"(c[2]), "+f"(c[3])
                 : "r"(a[0]), "r"(a[1]), "r"(a[2]), "r"(a[3]), "r"(b[0]), "r"(b[1]));
}

__device__ __forceinline__ float sigm_f(float x) { return __fdividef(1.f, 1.f + __expf(-x)); }
__device__ __forceinline__ float tanh_f(float x) { return __fdividef(2.f, 1.f + __expf(-2.f * x)) - 1.f; }

// ============================================================
// gates GEMM (pipelined) + fused LSTM cell.
// ============================================================
__device__ void gates_body(
    int nbase,
    const __nv_bfloat16* A0, const __nv_bfloat16* W0, int ldw0,
    const __nv_bfloat16* A1, const __nv_bfloat16* W1, int ldw1,
    int npairs,
    const float* initp, long initStride, const float* bias,
    const int* lens, int t,
    const __nv_bfloat16* hin, __nv_bfloat16* hout, float* cf,
    __nv_bfloat16* nh_out, float* S_out, float* hf_out,
    __nv_bfloat16* As, __nv_bfloat16* Bs)
{
    const int tid = threadIdx.x, lane = tid & 31, wid = tid >> 5;
    const int m0 = (wid >> 2) * 64, warp_n = wid & 3;
    const unsigned as_base = (unsigned)__cvta_generic_to_shared(As);
    const unsigned bs_base = (unsigned)__cvta_generic_to_shared(Bs);
    const int ldrow = tid >> 3, ldc8 = (tid & 7) * 8;

    float c[4][4][4];
#pragma unroll
    for (int mi = 0; mi < 4; mi++)
#pragma unroll
        for (int ni = 0; ni < 4; ni++)
#pragma unroll
            for (int q = 0; q < 4; q++) c[mi][ni][q] = 0.f;

    uint4 ra[4], rb[4];
    const int total = npairs * 8;
    auto fetch = [&](int ch) {
        int p = ch >> 3, k0 = (ch & 7) * 64;
        const __nv_bfloat16* A = (p == 0) ? A0 : A1;
        const __nv_bfloat16* W = (p == 0) ? W0 : W1;
        int ldw = (p == 0) ? ldw0 : ldw1;
#pragma unroll
        for (int q = 0; q < 4; q++) {
            int row = q * 32 + ldrow;
            ra[q] = *reinterpret_cast<const uint4*>(&A[(long)row * 512 + k0 + ldc8]);
            int wrow = ((row >> 5) * 512) + nbase + (row & 31);
            rb[q] = *reinterpret_cast<const uint4*>(&W[(long)wrow * ldw + k0 + ldc8]);
        }
    };
    fetch(0);
    for (int ch = 0; ch < total; ch++) {
        __syncthreads();
#pragma unroll
        for (int q = 0; q < 4; q++) {
            int row = q * 32 + ldrow;
            *reinterpret_cast<uint4*>(&As[row * LSTRIDE + ldc8]) = ra[q];
            *reinterpret_cast<uint4*>(&Bs[row * LSTRIDE + ldc8]) = rb[q];
        }
        __syncthreads();
        if (ch + 1 < total) fetch(ch + 1);
#pragma unroll
        for (int ks = 0; ks < 4; ks++) {
            int koff = ks * 16;
            unsigned a[4][4], b[4][2];
#pragma unroll
            for (int mi = 0; mi < 4; mi++) {
                int r = m0 + mi * 16 + (lane & 15);
                int ccol = koff + (lane >> 4) * 8;
                ldsm4(a[mi], as_base + (unsigned)(r * LSTRIDE + ccol) * 2u);
            }
#pragma unroll
            for (int ni = 0; ni < 4; ni++) {
                int r = ni * 32 + warp_n * 8 + (lane & 7);
                int ccol = koff + ((lane >> 3) & 1) * 8;
                ldsm2(b[ni], bs_base + (unsigned)(r * LSTRIDE + ccol) * 2u);
            }
#pragma unroll
            for (int mi = 0; mi < 4; mi++)
#pragma unroll
                for (int ni = 0; ni < 4; ni++) mma16816(c[mi][ni], a[mi], b[ni]);
        }
    }

    // cell epilogue
#pragma unroll
    for (int mi = 0; mi < 4; mi++) {
#pragma unroll
        for (int t2 = 0; t2 < 2; t2++) {
            int row = m0 + mi * 16 + (lane >> 2) + 8 * t2;
#pragma unroll
            for (int u = 0; u < 2; u++) {
                int j = nbase + warp_n * 8 + 2 * (lane & 3) + u;
                int e = 2 * t2 + u;
                float gi = c[mi][0][e], gf = c[mi][1][e], gg = c[mi][2][e], go = c[mi][3][e];
                if (initp) {
                    const float* ip = initp + (long)row * initStride;
                    gi += ip[j]; gf += ip[512 + j]; gg += ip[1024 + j]; go += ip[1536 + j];
                }
                if (bias) {
                    gi += bias[j]; gf += bias[512 + j]; gg += bias[1024 + j]; go += bias[1536 + j];
                }
                float i_ = sigm_f(gi), f_ = sigm_f(gf), tg = tanh_f(gg), o_ = sigm_f(go);
                int idx = row * 512 + j;
                float cn = f_ * cf[idx] + i_ * tg;
                float hn = o_ * tanh_f(cn);
                bool mk = lens ? (t < lens[row]) : true;
                if (nh_out) nh_out[idx] = __float2bfloat16_rn(hn);
                if (S_out) S_out[(long)row * Lq * 512 + (long)t * 512 + j] = mk ? hn : 0.f;
                if (hf_out) hf_out[idx] = hn;
                if (mk) { cf[idx] = cn; hout[idx] = __float2bfloat16_rn(hn); }
                else hout[idx] = hin[idx];
            }
        }
    }
}

// ============================================================
// logits tile (pipelined) + exp-sum / target epilogue
// ============================================================
__device__ void logits_body(
    int tl, int ls, const __nv_bfloat16* avh, const float* out_b,
    const int* trg_tokens, __nv_bfloat16* As, __nv_bfloat16* Bs,
    int* stgt, float* red)
{
    const int tid = threadIdx.x, lane = tid & 31, wid = tid >> 5;
    const int m0 = (wid >> 2) * 64, warp_n = wid & 3;
    const int n0w = warp_n * 32;
    const int nblk0 = tl * 128;
    if (tid < 128) stgt[tid] = trg_tokens[tid * Tq + ls + 1];

    float c[4][4][4];
#pragma unroll
    for (int mi = 0; mi < 4; mi++)
#pragma unroll
        for (int ni = 0; ni < 4; ni++)
#pragma unroll
            for (int q = 0; q < 4; q++) c[mi][ni][q] = 0.f;

    const unsigned as_base = (unsigned)__cvta_generic_to_shared(As);
    const unsigned bs_base = (unsigned)__cvta_generic_to_shared(Bs);
    const int ldrow = tid >> 3, ldc8 = (tid & 7) * 8;

    uint4 ra[4], rb[4];
    auto fetch = [&](int kc) {
        int k0 = kc * 64;
#pragma unroll
        for (int q = 0; q < 4; q++) {
            int row = q * 32 + ldrow;
            ra[q] = *reinterpret_cast<const uint4*>(&avh[row * KP + k0 + ldc8]);
            rb[q] = *reinterpret_cast<const uint4*>(&g_outWb[(long)(nblk0 + row) * KP + k0 + ldc8]);
        }
    };
    fetch(0);
    for (int kc = 0; kc < 8; kc++) {
        __syncthreads();
#pragma unroll
        for (int q = 0; q < 4; q++) {
            int row = q * 32 + ldrow;
            *reinterpret_cast<uint4*>(&As[row * LSTRIDE + ldc8]) = ra[q];
            *reinterpret_cast<uint4*>(&Bs[row * LSTRIDE + ldc8]) = rb[q];
        }
        __syncthreads();
        if (kc + 1 < 8) fetch(kc + 1);
#pragma unroll
        for (int ks = 0; ks < 4; ks++) {
            int koff = ks * 16;
            unsigned a[4][4], b[4][2];
#pragma unroll
            for (int mi = 0; mi < 4; mi++) {
                int r = m0 + mi * 16 + (lane & 15);
                int ccol = koff + (lane >> 4) * 8;
                ldsm4(a[mi], as_base + (unsigned)(r * LSTRIDE + ccol) * 2u);
            }
#pragma unroll
            for (int ni = 0; ni < 4; ni++) {
                int r = n0w + ni * 8 + (lane & 7);
                int ccol = koff + ((lane >> 3) & 1) * 8;
                ldsm2(b[ni], bs_base + (unsigned)(r * LSTRIDE + ccol) * 2u);
            }
#pragma unroll
            for (int mi = 0; mi < 4; mi++)
#pragma unroll
                for (int ni = 0; ni < 4; ni++) mma16816(c[mi][ni], a[mi], b[ni]);
        }
    }
    __syncthreads();

    const int gid = lane >> 2, tig = lane & 3;
#pragma unroll
    for (int mi = 0; mi < 4; mi++) {
        int r0 = m0 + mi * 16 + gid;
        int r1 = r0 + 8;
        int t0 = stgt[r0], t1 = stgt[r1];
        float s0 = 0.f, s1 = 0.f;
#pragma unroll
        for (int ni = 0; ni < 4; ni++) {
            int n = nblk0 + n0w + ni * 8 + tig * 2;
            float b0 = out_b[n], b1 = out_b[n + 1];
            float l00 = c[mi][ni][0] + b0, l01 = c[mi][ni][1] + b1;
            float l10 = c[mi][ni][2] + b0, l11 = c[mi][ni][3] + b1;
            s0 += __expf(l00) + __expf(l01);
            s1 += __expf(l10) + __expf(l11);
            if (n == t0) g_tgtlogit[r0] = l00;
            if (n + 1 == t0) g_tgtlogit[r0] = l01;
            if (n == t1) g_tgtlogit[r1] = l10;
            if (n + 1 == t1) g_tgtlogit[r1] = l11;
        }
        s0 += __shfl_xor_sync(0xffffffffu, s0, 1);
        s0 += __shfl_xor_sync(0xffffffffu, s0, 2);
        s1 += __shfl_xor_sync(0xffffffffu, s1, 1);
        s1 += __shfl_xor_sync(0xffffffffu, s1, 2);
        if (tig == 0) { red[r0 * 4 + warp_n] = s0; red[r1 * 4 + warp_n] = s1; }
    }
    __syncthreads();
    if (tid < 128)
        g_part[tl * Bq + tid] = red[tid * 4] + red[tid * 4 + 1] + red[tid * 4 + 2] + red[tid * 4 + 3];
}

// ============================================================
// hid h-part tile: g_avf[:, nblk0:+128] = dh@hidW_left^T + hid_b
// ============================================================
__device__ void hidL_body(
    int nblk0, const __nv_bfloat16* A, const float* hid_b,
    __nv_bfloat16* As, __nv_bfloat16* Bs)
{
    const int tid = threadIdx.x, lane = tid & 31, wid = tid >> 5;
    const int m0 = (wid >> 2) * 64, warp_n = wid & 3;

    float c[4][4][4];
#pragma unroll
    for (int mi = 0; mi < 4; mi++)
#pragma unroll
        for (int ni = 0; ni < 4; ni++)
#pragma unroll
            for (int q = 0; q < 4; q++) c[mi][ni][q] = 0.f;

    const unsigned as_base = (unsigned)__cvta_generic_to_shared(As);
    const unsigned bs_base = (unsigned)__cvta_generic_to_shared(Bs);
    const int ldrow = tid >> 3, ldc8 = (tid & 7) * 8;

    uint4 ra[4], rb[4];
    auto fetch = [&](int kc) {
        int k0 = kc * 64;
#pragma unroll
        for (int q = 0; q < 4; q++) {
            int row = q * 32 + ldrow;
            ra[q] = *reinterpret_cast<const uint4*>(&A[(long)row * 512 + k0 + ldc8]);
            rb[q] = *reinterpret_cast<const uint4*>(&g_hidWb[(long)(nblk0 + row) * 1024 + k0 + ldc8]);
        }
    };
    fetch(0);
    for (int kc = 0; kc < 8; kc++) {
        __syncthreads();
#pragma unroll
        for (int q = 0; q < 4; q++) {
            int row = q * 32 + ldrow;
            *reinterpret_cast<uint4*>(&As[row * LSTRIDE + ldc8]) = ra[q];
            *reinterpret_cast<uint4*>(&Bs[row * LSTRIDE + ldc8]) = rb[q];
        }
        __syncthreads();
        if (kc + 1 < 8) fetch(kc + 1);
#pragma unroll
        for (int ks = 0; ks < 4; ks++) {
            int koff = ks * 16;
            unsigned a[4][4], b[4][2];
#pragma unroll
            for (int mi = 0; mi < 4; mi++) {
                int r = m0 + mi * 16 + (lane & 15);
                int ccol = koff + (lane >> 4) * 8;
                ldsm4(a[mi], as_base + (unsigned)(r * LSTRIDE + ccol) * 2u);
            }
#pragma unroll
            for (int ni = 0; ni < 4; ni++) {
                int r = warp_n * 32 + ni * 8 + (lane & 7);
                int ccol = koff + ((lane >> 3) & 1) * 8;
                ldsm2(b[ni], bs_base + (unsigned)(r * LSTRIDE + ccol) * 2u);
            }
#pragma unroll
            for (int mi = 0; mi < 4; mi++)
#pragma unroll
                for (int ni = 0; ni < 4; ni++) mma16816(c[mi][ni], a[mi], b[ni]);
        }
    }

#pragma unroll
    for (int mi = 0; mi < 4; mi++)
#pragma unroll
        for (int ni = 0; ni < 4; ni++)
#pragma unroll
            for (int t2 = 0; t2 < 2; t2++) {
                int gm = m0 + mi * 16 + (lane >> 2) + 8 * t2;
#pragma unroll
                for (int u = 0; u < 2; u++) {
                    int n = nblk0 + warp_n * 32 + ni * 8 + 2 * (lane & 3) + u;
                    g_avf[(long)gm * Hq + n] = c[mi][ni][2 * t2 + u] + hid_b[n];
                }
            }
}

// ============================================================
// encoder wavefront: blocks 0-15 layer0(t0), blocks 16-31 layer1(t1)
// ============================================================
__global__ __launch_bounds__(256) void enc_wave_k(
    int t0, int t1, const int* __restrict__ src_lens, const float* __restrict__ enc_b1)
{
    __shared__ __nv_bfloat16 As[128 * LSTRIDE];
    __shared__ __nv_bfloat16 Bs[128 * LSTRIDE];
    const int nbase = (blockIdx.x & 15) * 32;
    if (blockIdx.x < 16) {
        if (t0 < 0) return;
        int p = t0 & 1;
        gates_body(nbase, g_h1b[p], g_Whh0b, 512,
                   nullptr, nullptr, 0, 1,
                   g_G0 + (long)t0 * G4, (long)Lq * G4, nullptr, src_lens, t0,
                   g_h1b[p], g_h1b[1 - p], g_c1, g_nh1b, nullptr, nullptr, As, Bs);
    } else {
        if (t1 < 0) return;
        int p = t1 & 1;
        gates_body(nbase, g_nh1b, g_Wih1b, 512,
                   g_h2b[p], g_Whh1b, 512, 2,
                   nullptr, 0, enc_b1, src_lens, t1,
                   g_h2b[p], g_h2b[1 - p], g_c2, nullptr, g_S, nullptr, As, Bs);
    }
}

// ============================================================
// decoder main: blocks 0-15 gates(s), blocks 16-265 logits(s-1)
// ============================================================
__global__ __launch_bounds__(256) void dec_main_k(
    int s, const int* __restrict__ trg_tokens, const float* __restrict__ out_b)
{
    __shared__ __nv_bfloat16 As[128 * LSTRIDE];
    __shared__ __nv_bfloat16 Bs[128 * LSTRIDE];
    __shared__ int stgt[128];
    __shared__ float red[512];
    if (blockIdx.x < 16) {
        if (s > Tq - 2) return;
        int p = s & 1;
        gates_body(blockIdx.x * 32,
                   g_avh[p], g_dWihb + 512, 1024,
                   g_dhb[p], g_dWhhb, 512, 2,
                   g_GV + (long)s * Bq * G4, (long)G4, nullptr, nullptr, 0,
                   g_dhb[p], g_dhb[1 - p], g_dc, nullptr, nullptr, g_dh, As, Bs);
    } else {
        int ls = s - 1;
        if (ls < 0) return;
        logits_body(blockIdx.x - 16, ls, g_avh[s & 1], out_b, trg_tokens, As, Bs, stgt, red);
    }
}

// ============================================================
// attn (0-127) + combine(s-1) (128) + hid h-part (129-132)
// ============================================================
__global__ __launch_bounds__(256) void attn_combine_k(
    int s, const int* __restrict__ src_lens, const int* __restrict__ trg_lens,
    const float* __restrict__ hid_b)
{
    __shared__ __align__(16) char raw[36864];
    int tid = threadIdx.x;
    if (blockIdx.x < 128) {
        if (s > Tq - 2) return;
        float* sh = (float*)raw;
        float* part = sh + 512;
        float* sc = part + 256;
        float* sinv = sc + 64;
        int b = blockIdx.x;
        sh[tid] = g_dh[(long)b * Hq + tid];
        sh[tid + 256] = g_dh[(long)b * Hq + tid + 256];
        __syncthreads();
        int l = tid >> 2, q = tid & 3;
        const float* Sb = g_S + (long)b * Lq * Hq + (long)l * Hq + q * 128;
        float pv = 0.f;
#pragma unroll 8
        for (int k = 0; k < 128; k++) pv = fmaf(sh[q * 128 + k], Sb[k], pv);
        part[l * 4 + q] = pv;
        __syncthreads();
        if (tid < Lq) {
            float sv = part[tid * 4] + part[tid * 4 + 1] + part[tid * 4 + 2] + part[tid * 4 + 3];
            if (tid >= src_lens[b]) sv = -1e9f;
            sc[tid] = __expf(sv);
        }
        __syncthreads();
        if (tid == 0) {
            float ts = 0.f;
            for (int i = 0; i < Lq; i++) ts += sc[i];
            *sinv = 1.f / ts;
        }
        __syncthreads();
        if (tid < Lq) sc[tid] *= *sinv;
        __syncthreads();
        for (int j = tid; j < Hq; j += 256) {
            const float* Sb2 = g_S + (long)b * Lq * Hq + j;
            float acc = 0.f;
#pragma unroll 8
            for (int l2 = 0; l2 < Lq; l2++) acc = fmaf(sc[l2], Sb2[(long)l2 * Hq], acc);
            g_ctxb[(long)b * Hq + j] = __float2bfloat16_rn(acc);
        }
    } else if (blockIdx.x == 128) {
        int ls = s - 1;
        if (ls < 0) return;
        int b = tid;
        if (b < 128) {
            float tot = 0.f;
            for (int i = 0; i < NTILES; i++) tot += g_part[i * Bq + b];
            float nll = logf(tot) - g_tgtlogit[b];
            g_nllbuf[ls * Bq + b] = ((ls + 1) < trg_lens[b]) ? -nll : 0.f;
        }
    } else {
        if (s > Tq - 2) return;
        __nv_bfloat16* As = (__nv_bfloat16*)raw;
        __nv_bfloat16* Bs = As + 128 * LSTRIDE;
        hidL_body((blockIdx.x - 129) * 128, g_dhb[(s + 1) & 1], hid_b, As, Bs);
    }
}

// ============================================================
// standalone bf16 GEMM (pipelined, gather-free, optional init)
// ============================================================
__global__ __launch_bounds__(256) void hgemm_k(
    const __nv_bfloat16* __restrict__ A0, const __nv_bfloat16* __restrict__ W0, int ldw0,
    const __nv_bfloat16* __restrict__ A1, const __nv_bfloat16* __restrict__ W1, int ldw1,
    int npairs,
    const float* __restrict__ initp,
    const float* __restrict__ bias, int N,
    float* __restrict__ outRaw, float* __restrict__ outTanhF,
    __nv_bfloat16* __restrict__ outBF)
{
    __shared__ __nv_bfloat16 As[128 * LSTRIDE];
    __shared__ __nv_bfloat16 Bs[128 * LSTRIDE];
    const int tid = threadIdx.x, lane = tid & 31, wid = tid >> 5;
    const int m0 = (wid >> 2) * 64, warp_n = wid & 3;
    const int mblk0 = blockIdx.x * 128, nblk0 = blockIdx.y * 128;

    float c[4][4][4];
#pragma unroll
    for (int mi = 0; mi < 4; mi++)
#pragma unroll
        for (int ni = 0; ni < 4; ni++)
#pragma unroll
            for (int q = 0; q < 4; q++) c[mi][ni][q] = 0.f;

    const unsigned as_base = (unsigned)__cvta_generic_to_shared(As);
    const unsigned bs_base = (unsigned)__cvta_generic_to_shared(Bs);
    const int ldrow = tid >> 3, ldc8 = (tid & 7) * 8;

    uint4 ra[4], rb[4];
    const int total = npairs * 8;
    auto fetch = [&](int ch) {
        int p = ch >> 3, k0 = (ch & 7) * 64;
        const __nv_bfloat16* A = (p == 0) ? A0 : A1;
        const __nv_bfloat16* W = (p == 0) ? W0 : W1;
        int ldw = (p == 0) ? ldw0 : ldw1;
#pragma unroll
        for (int q = 0; q < 4; q++) {
            int row = q * 32 + ldrow;
            int gm = mblk0 + row;
            ra[q] = *reinterpret_cast<const uint4*>(&A[(long)gm * 512 + k0 + ldc8]);
            rb[q] = *reinterpret_cast<const uint4*>(&W[(long)(nblk0 + row) * ldw + k0 + ldc8]);
        }
    };
    fetch(0);
    for (int ch = 0; ch < total; ch++) {
        __syncthreads();
#pragma unroll
        for (int q = 0; q < 4; q++) {
            int row = q * 32 + ldrow;
            *reinterpret_cast<uint4*>(&As[row * LSTRIDE + ldc8]) = ra[q];
            *reinterpret_cast<uint4*>(&Bs[row * LSTRIDE + ldc8]) = rb[q];
        }
        __syncthreads();
        if (ch + 1 < total) fetch(ch + 1);
#pragma unroll
        for (int ks = 0; ks < 4; ks++) {
            int koff = ks * 16;
            unsigned a[4][4], b[4][2];
#pragma unroll
            for (int mi = 0; mi < 4; mi++) {
                int r = m0 + mi * 16 + (lane & 15);
                int ccol = koff + (lane >> 4) * 8;
                ldsm4(a[mi], as_base + (unsigned)(r * LSTRIDE + ccol) * 2u);
            }
#pragma unroll
            for (int ni = 0; ni < 4; ni++) {
                int r = warp_n * 32 + ni * 8 + (lane & 7);
                int ccol = koff + ((lane >> 3) & 1) * 8;
                ldsm2(b[ni], bs_base + (unsigned)(r * LSTRIDE + ccol) * 2u);
            }
#pragma unroll
            for (int mi = 0; mi < 4; mi++)
#pragma unroll
                for (int ni = 0; ni < 4; ni++) mma16816(c[mi][ni], a[mi], b[ni]);
        }
    }

#pragma unroll
    for (int mi = 0; mi < 4; mi++)
#pragma unroll
        for (int ni = 0; ni < 4; ni++)
#pragma unroll
            for (int t2 = 0; t2 < 2; t2++) {
                int gm = mblk0 + m0 + mi * 16 + (lane >> 2) + 8 * t2;
#pragma unroll
                for (int u = 0; u < 2; u++) {
                    int n = nblk0 + warp_n * 32 + ni * 8 + 2 * (lane & 3) + u;
                    float v = c[mi][ni][2 * t2 + u];
                    long oi = (long)gm * N + n;
                    if (initp) v += initp[oi];
                    if (bias) v += bias[n];
                    if (outRaw) outRaw[oi] = v;
                    float tv = v;
                    if (outTanhF) { tv = tanhf(v); outTanhF[oi] = tv; }
                    if (outBF) outBF[oi] = __float2bfloat16_rn(outTanhF ? tv : v);
                }
            }
}

// ---------------- gather-convert (compact embedding rows) ----------------
__global__ void gather_src_k(const float* __restrict__ emb, const int* __restrict__ toks)
{
    int m = blockIdx.x;
    int tok = toks[m];
    const float2* src = reinterpret_cast<const float2*>(emb + (long)tok * Eq);
    __nv_bfloat162* dst = reinterpret_cast<__nv_bfloat162*>(g_xsB + (long)m * Eq);
    float2 v = src[threadIdx.x];
    dst[threadIdx.x] = __floats2bfloat162_rn(v.x, v.y);
}
__global__ void gather_trg_k(const float* __restrict__ emb, const int* __restrict__ toks)
{
    int m = blockIdx.x;
    int s = m >> 7, b = m & 127;
    int tok = toks[b * Tq + s];
    const float2* src = reinterpret_cast<const float2*>(emb + (long)tok * Eq);
    __nv_bfloat162* dst = reinterpret_cast<__nv_bfloat162*>(g_vembB + (long)m * Eq);
    float2 v = src[threadIdx.x];
    dst[threadIdx.x] = __floats2bfloat162_rn(v.x, v.y);
}

// ---------------- misc ----------------
__global__ void zero_k()
{
    int i = blockIdx.x * 256 + threadIdx.x;
    if (i < HB) {
        g_h1b[0][i] = __float2bfloat16(0.f);
        g_h2b[0][i] = __float2bfloat16(0.f);
        g_avh[0][i] = __float2bfloat16(0.f);
        g_c1[i] = 0.f; g_c2[i] = 0.f;
    }
}

__global__ void f2bf_k(const float* __restrict__ in, __nv_bfloat16* __restrict__ out, int n)
{
    int i = blockIdx.x * 256 + threadIdx.x;
    if (i < n) out[i] = __float2bfloat16_rn(in[i]);
}

__global__ __launch_bounds__(256) void reduce_k(float* __restrict__ out)
{
    __shared__ float sm[256];
    float t = 0.f;
    for (int i = threadIdx.x; i < (Tq - 1) * Bq; i += 256) t += g_nllbuf[i];
    sm[threadIdx.x] = t;
    __syncthreads();
    for (int st = 128; st > 0; st >>= 1) {
        if (threadIdx.x < st) sm[threadIdx.x] += sm[threadIdx.x + st];
        __syncthreads();
    }
    if (threadIdx.x == 0) out[0] = sm[0];
}

// ---------------- launch ----------------
extern "C" void kernel_launch(void* const* d_in, const int* in_sizes, int n_in,
                              void* d_out, int out_size)
{
    const int*   src_tokens = (const int*)d_in[0];
    const int*   src_lens   = (const int*)d_in[1];
    const int*   trg_tokens = (const int*)d_in[2];
    const int*   trg_lens   = (const int*)d_in[3];
    const float* src_emb    = (const float*)d_in[4];
    const float* trg_emb    = (const float*)d_in[5];
    const float* enc_Wih0   = (const float*)d_in[6];
    const float* enc_Whh0   = (const float*)d_in[7];
    const float* enc_b0     = (const float*)d_in[8];
    const float* enc_Wih1   = (const float*)d_in[9];
    const float* enc_Whh1   = (const float*)d_in[10];
    const float* enc_b1     = (const float*)d_in[11];
    const float* dec_Wih    = (const float*)d_in[12];
    const float* dec_Whh    = (const float*)d_in[13];
    const float* dec_b      = (const float*)d_in[14];
    const float* hid_W      = (const float*)d_in[15];
    const float* hid_b      = (const float*)d_in[16];
    const float* out_W      = (const float*)d_in[17];
    const float* out_b      = (const float*)d_in[18];
    const float* init_W     = (const float*)d_in[19];
    const float* init_b     = (const float*)d_in[20];

    float *G0, *GV, *c1, *c2, *dc, *dh, *avf;
    __nv_bfloat16 *Wih0b, *Whh0b, *Wih1b, *Whh1b, *dWihb, *dWhhb, *hidWb, *initWb;
    __nv_bfloat16 *outWb, *c1b, *c2b, *dhb0, *ctxb, *avh0, *xsB, *vembB;
    cudaGetSymbolAddress((void**)&G0, g_G0);
    cudaGetSymbolAddress((void**)&GV, g_GV);
    cudaGetSymbolAddress((void**)&c1, g_c1);
    cudaGetSymbolAddress((void**)&c2, g_c2);
    cudaGetSymbolAddress((void**)&dc, g_dc);
    cudaGetSymbolAddress((void**)&dh, g_dh);
    cudaGetSymbolAddress((void**)&avf, g_avf);
    cudaGetSymbolAddress((void**)&Wih0b, g_Wih0b);
    cudaGetSymbolAddress((void**)&Whh0b, g_Whh0b);
    cudaGetSymbolAddress((void**)&Wih1b, g_Wih1b);
    cudaGetSymbolAddress((void**)&Whh1b, g_Whh1b);
    cudaGetSymbolAddress((void**)&dWihb, g_dWihb);
    cudaGetSymbolAddress((void**)&dWhhb, g_dWhhb);
    cudaGetSymbolAddress((void**)&hidWb, g_hidWb);
    cudaGetSymbolAddress((void**)&initWb, g_initWb);
    cudaGetSymbolAddress((void**)&outWb, g_outWb);
    cudaGetSymbolAddress((void**)&c1b, g_c1b);
    cudaGetSymbolAddress((void**)&c2b, g_c2b);
    cudaGetSymbolAddress((void**)&dhb0, g_dhb);
    cudaGetSymbolAddress((void**)&ctxb, g_ctxb);
    cudaGetSymbolAddress((void**)&avh0, g_avh);
    cudaGetSymbolAddress((void**)&xsB, g_xsB);
    cudaGetSymbolAddress((void**)&vembB, g_vembB);
    __nv_bfloat16* dhb[2] = {dhb0, dhb0 + HB};
    __nv_bfloat16* avh[2] = {avh0, avh0 + HB};

    const int cb = (HB + 255) / 256;

    zero_k<<<cb, 256>>>();

    // weight conversions
    f2bf_k<<<(G4 * KP + 255) / 256, 256>>>(enc_Wih0, Wih0b, G4 * KP);
    f2bf_k<<<(G4 * KP + 255) / 256, 256>>>(enc_Whh0, Whh0b, G4 * KP);
    f2bf_k<<<(G4 * KP + 255) / 256, 256>>>(enc_Wih1, Wih1b, G4 * KP);
    f2bf_k<<<(G4 * KP + 255) / 256, 256>>>(enc_Whh1, Whh1b, G4 * KP);
    f2bf_k<<<(G4 * 1024 + 255) / 256, 256>>>(dec_Wih, dWihb, G4 * 1024);
    f2bf_k<<<(G4 * KP + 255) / 256, 256>>>(dec_Whh, dWhhb, G4 * KP);
    f2bf_k<<<(Hq * 1024 + 255) / 256, 256>>>(hid_W, hidWb, Hq * 1024);
    f2bf_k<<<(Hq * 1024 + 255) / 256, 256>>>(init_W, initWb, Hq * 1024);
    f2bf_k<<<(Vq * KP + 255) / 256, 256>>>(out_W, outWb, Vq * KP);

    // compact embedding gathers (bf16)
    gather_src_k<<<Bq * Lq, 256>>>(src_emb, src_tokens);
    gather_trg_k<<<(Tq - 1) * Bq, 256>>>(trg_emb, trg_tokens);

    // G0 = xs @ Wih0^T + b0   (M=8192, N=2048)
    hgemm_k<<<dim3(Bq * Lq / 128, G4 / 128), 256>>>(
        xsB, Wih0b, KP, nullptr, nullptr, 0, 1,
        nullptr, enc_b0, G4, G0, nullptr, nullptr);

    // GV = vemb @ dec_Wih_left^T + dec_b   (M=6016, N=2048)
    hgemm_k<<<dim3((Tq - 1) * Bq / 128, G4 / 128), 256>>>(
        vembB, dWihb, 1024, nullptr, nullptr, 0, 1,
        nullptr, dec_b, G4, GV, nullptr, nullptr);

    // ---------------- encoder wavefront ----------------
    for (int t = 0; t <= Lq; t++)
        enc_wave_k<<<32, 256>>>(t < Lq ? t : -1, t - 1, src_lens, enc_b1);

    // decoder init: c0 = [c1,c2] @ init_W^T + init_b ; h0 = tanh(c0)
    f2bf_k<<<cb, 256>>>(c1, c1b, HB);
    f2bf_k<<<cb, 256>>>(c2, c2b, HB);
    hgemm_k<<<dim3(1, Hq / 128), 256>>>(
        c1b, initWb, 1024, c2b, initWb + 512, 1024, 2,
        nullptr, init_b, Hq, dc, dh, dhb[0]);

    // ---------------- decoder ----------------
    for (int s = 0; s < Tq - 1; s++) {
        dec_main_k<<<16 + NTILES, 256>>>(s, trg_tokens, out_b);
        attn_combine_k<<<133, 256>>>(s, src_lens, trg_lens, hid_b);
        // avh = avf(h-part) + ctx @ hidW_right^T
        hgemm_k<<<dim3(1, Hq / 128), 256>>>(
            ctxb, hidWb + 512, 1024, nullptr, nullptr, 0, 1,
            avf, nullptr, Hq, nullptr, nullptr, avh[(s + 1) & 1]);
    }
    // tail: logits(T-2) + combine(T-2)
    dec_main_k<<<16 + NTILES, 256>>>(Tq - 1, trg_tokens, out_b);
    attn_combine_k<<<133, 256>>>(Tq - 1, src_lens, trg_lens, hid_b);

    reduce_k<<<1, 256>>>((float*)d_out);
}

// round 10
// speedup vs baseline: 2.7522x; 1.0177x over previous
#include <cuda_runtime.h>
#include <cuda_bf16.h>
#include <math.h>
#include <stdint.h>

#define Bq 128
#define Lq 64
#define Tq 48
#define Eq 512
#define Hq 512
#define Vq 32000
#define G4 2048
#define KP 512
#define NTILES 250
#define LHALF 125
#define LSTRIDE 72
#define HB (Bq * Hq)
#define GVTILES ((Tq - 1) * 16)   // 47 M-tiles x 16 N-tiles = 752

// ---------------- fp32 scratch ----------------
__device__ float g_G0[Bq * Lq * G4];
__device__ float g_GV[(Tq - 1) * Bq * G4];
__device__ float g_c1[HB], g_c2[HB];
__device__ float g_S[Bq * Lq * Hq];
__device__ float g_dh[HB], g_dc[HB];
__device__ float g_avf[HB];
__device__ float g_nllbuf[(Tq - 1) * Bq];
__device__ float g_part[NTILES * Bq];
__device__ float g_tgtlogit[Bq];

// ---------------- bf16 weights ----------------
__device__ __nv_bfloat16 g_Wih0b[G4 * KP], g_Whh0b[G4 * KP];
__device__ __nv_bfloat16 g_Wih1b[G4 * KP], g_Whh1b[G4 * KP];
__device__ __nv_bfloat16 g_dWihb[G4 * 1024], g_dWhhb[G4 * KP];
__device__ __nv_bfloat16 g_hidWb[Hq * 1024], g_initWb[Hq * 1024];
__device__ __nv_bfloat16 g_outWb[Vq * KP];

// ---------------- compact gathered embeddings (bf16) ----------------
__device__ __nv_bfloat16 g_xsB[Bq * Lq * Eq];
__device__ __nv_bfloat16 g_vembB[(Tq - 1) * Bq * Eq];

// ---------------- bf16 states ----------------
__device__ __nv_bfloat16 g_h1b[2][HB], g_h2b[2][HB], g_dhb[2][HB];
__device__ __nv_bfloat16 g_nh1b[HB];
__device__ __nv_bfloat16 g_c1b[HB], g_c2b[HB];
__device__ __nv_bfloat16 g_ctxb[HB];
__device__ __nv_bfloat16 g_avh[2][HB];

// ---------------- MMA helpers ----------------
__device__ __forceinline__ void ldsm4(unsigned* r, unsigned addr) {
    asm volatile("ldmatrix.sync.aligned.m8n8.x4.shared.b16 {%0,%1,%2,%3}, [%4];"
                 : "=r"(r[0]), "=r"(r[1]), "=r"(r[2]), "=r"(r[3]) : "r"(addr));
}
__device__ __forceinline__ void ldsm2(unsigned* r, unsigned addr) {
    asm volatile("ldmatrix.sync.aligned.m8n8.x2.shared.b16 {%0,%1}, [%2];"
                 : "=r"(r[0]), "=r"(r[1]) : "r"(addr));
}
__device__ __forceinline__ void mma16816(float* c, const unsigned* a, const unsigned* b) {
    asm volatile("mma.sync.aligned.m16n8k16.row.col.f32.bf16.bf16.f32 "
                 "{%0,%1,%2,%3}, {%4,%5,%6,%7}, {%8,%9}, {%0,%1,%2,%3};"
                 : "+f"(c[0]), "+f"(c[1]), "+f"(c[2]), "+f"(c[3])
                 : "r"(a[0]), "r"(a[1]), "r"(a[2]), "r"(a[3]), "r"(b[0]), "r"(b[1]));
}

__device__ __forceinline__ float sigm_f(float x) { return __fdividef(1.f, 1.f + __expf(-x)); }
__device__ __forceinline__ float tanh_f(float x) { return __fdividef(2.f, 1.f + __expf(-2.f * x)) - 1.f; }

// ============================================================
// gates GEMM (pipelined) + fused LSTM cell.
// ============================================================
__device__ void gates_body(
    int nbase,
    const __nv_bfloat16* A0, const __nv_bfloat16* W0, int ldw0,
    const __nv_bfloat16* A1, const __nv_bfloat16* W1, int ldw1,
    int npairs,
    const float* initp, long initStride, const float* bias,
    const int* lens, int t,
    const __nv_bfloat16* hin, __nv_bfloat16* hout, float* cf,
    __nv_bfloat16* nh_out, float* S_out, float* hf_out,
    __nv_bfloat16* As, __nv_bfloat16* Bs)
{
    const int tid = threadIdx.x, lane = tid & 31, wid = tid >> 5;
    const int m0 = (wid >> 2) * 64, warp_n = wid & 3;
    const unsigned as_base = (unsigned)__cvta_generic_to_shared(As);
    const unsigned bs_base = (unsigned)__cvta_generic_to_shared(Bs);
    const int ldrow = tid >> 3, ldc8 = (tid & 7) * 8;

    float c[4][4][4];
#pragma unroll
    for (int mi = 0; mi < 4; mi++)
#pragma unroll
        for (int ni = 0; ni < 4; ni++)
#pragma unroll
            for (int q = 0; q < 4; q++) c[mi][ni][q] = 0.f;

    uint4 ra[4], rb[4];
    const int total = npairs * 8;
    auto fetch = [&](int ch) {
        int p = ch >> 3, k0 = (ch & 7) * 64;
        const __nv_bfloat16* A = (p == 0) ? A0 : A1;
        const __nv_bfloat16* W = (p == 0) ? W0 : W1;
        int ldw = (p == 0) ? ldw0 : ldw1;
#pragma unroll
        for (int q = 0; q < 4; q++) {
            int row = q * 32 + ldrow;
            ra[q] = *reinterpret_cast<const uint4*>(&A[(long)row * 512 + k0 + ldc8]);
            int wrow = ((row >> 5) * 512) + nbase + (row & 31);
            rb[q] = *reinterpret_cast<const uint4*>(&W[(long)wrow * ldw + k0 + ldc8]);
        }
    };
    fetch(0);
    for (int ch = 0; ch < total; ch++) {
        __syncthreads();
#pragma unroll
        for (int q = 0; q < 4; q++) {
            int row = q * 32 + ldrow;
            *reinterpret_cast<uint4*>(&As[row * LSTRIDE + ldc8]) = ra[q];
            *reinterpret_cast<uint4*>(&Bs[row * LSTRIDE + ldc8]) = rb[q];
        }
        __syncthreads();
        if (ch + 1 < total) fetch(ch + 1);
#pragma unroll
        for (int ks = 0; ks < 4; ks++) {
            int koff = ks * 16;
            unsigned a[4][4], b[4][2];
#pragma unroll
            for (int mi = 0; mi < 4; mi++) {
                int r = m0 + mi * 16 + (lane & 15);
                int ccol = koff + (lane >> 4) * 8;
                ldsm4(a[mi], as_base + (unsigned)(r * LSTRIDE + ccol) * 2u);
            }
#pragma unroll
            for (int ni = 0; ni < 4; ni++) {
                int r = ni * 32 + warp_n * 8 + (lane & 7);
                int ccol = koff + ((lane >> 3) & 1) * 8;
                ldsm2(b[ni], bs_base + (unsigned)(r * LSTRIDE + ccol) * 2u);
            }
#pragma unroll
            for (int mi = 0; mi < 4; mi++)
#pragma unroll
                for (int ni = 0; ni < 4; ni++) mma16816(c[mi][ni], a[mi], b[ni]);
        }
    }

    // cell epilogue
#pragma unroll
    for (int mi = 0; mi < 4; mi++) {
#pragma unroll
        for (int t2 = 0; t2 < 2; t2++) {
            int row = m0 + mi * 16 + (lane >> 2) + 8 * t2;
#pragma unroll
            for (int u = 0; u < 2; u++) {
                int j = nbase + warp_n * 8 + 2 * (lane & 3) + u;
                int e = 2 * t2 + u;
                float gi = c[mi][0][e], gf = c[mi][1][e], gg = c[mi][2][e], go = c[mi][3][e];
                if (initp) {
                    const float* ip = initp + (long)row * initStride;
                    gi += ip[j]; gf += ip[512 + j]; gg += ip[1024 + j]; go += ip[1536 + j];
                }
                if (bias) {
                    gi += bias[j]; gf += bias[512 + j]; gg += bias[1024 + j]; go += bias[1536 + j];
                }
                float i_ = sigm_f(gi), f_ = sigm_f(gf), tg = tanh_f(gg), o_ = sigm_f(go);
                int idx = row * 512 + j;
                float cn = f_ * cf[idx] + i_ * tg;
                float hn = o_ * tanh_f(cn);
                bool mk = lens ? (t < lens[row]) : true;
                if (nh_out) nh_out[idx] = __float2bfloat16_rn(hn);
                if (S_out) S_out[(long)row * Lq * 512 + (long)t * 512 + j] = mk ? hn : 0.f;
                if (hf_out) hf_out[idx] = hn;
                if (mk) { cf[idx] = cn; hout[idx] = __float2bfloat16_rn(hn); }
                else hout[idx] = hin[idx];
            }
        }
    }
}

// ============================================================
// logits tile (pipelined) + exp-sum / target epilogue
// ============================================================
__device__ void logits_body(
    int tl, int ls, const __nv_bfloat16* avh, const float* out_b,
    const int* trg_tokens, __nv_bfloat16* As, __nv_bfloat16* Bs,
    int* stgt, float* red)
{
    const int tid = threadIdx.x, lane = tid & 31, wid = tid >> 5;
    const int m0 = (wid >> 2) * 64, warp_n = wid & 3;
    const int n0w = warp_n * 32;
    const int nblk0 = tl * 128;
    if (tid < 128) stgt[tid] = trg_tokens[tid * Tq + ls + 1];

    float c[4][4][4];
#pragma unroll
    for (int mi = 0; mi < 4; mi++)
#pragma unroll
        for (int ni = 0; ni < 4; ni++)
#pragma unroll
            for (int q = 0; q < 4; q++) c[mi][ni][q] = 0.f;

    const unsigned as_base = (unsigned)__cvta_generic_to_shared(As);
    const unsigned bs_base = (unsigned)__cvta_generic_to_shared(Bs);
    const int ldrow = tid >> 3, ldc8 = (tid & 7) * 8;

    uint4 ra[4], rb[4];
    auto fetch = [&](int kc) {
        int k0 = kc * 64;
#pragma unroll
        for (int q = 0; q < 4; q++) {
            int row = q * 32 + ldrow;
            ra[q] = *reinterpret_cast<const uint4*>(&avh[row * KP + k0 + ldc8]);
            rb[q] = *reinterpret_cast<const uint4*>(&g_outWb[(long)(nblk0 + row) * KP + k0 + ldc8]);
        }
    };
    fetch(0);
    for (int kc = 0; kc < 8; kc++) {
        __syncthreads();
#pragma unroll
        for (int q = 0; q < 4; q++) {
            int row = q * 32 + ldrow;
            *reinterpret_cast<uint4*>(&As[row * LSTRIDE + ldc8]) = ra[q];
            *reinterpret_cast<uint4*>(&Bs[row * LSTRIDE + ldc8]) = rb[q];
        }
        __syncthreads();
        if (kc + 1 < 8) fetch(kc + 1);
#pragma unroll
        for (int ks = 0; ks < 4; ks++) {
            int koff = ks * 16;
            unsigned a[4][4], b[4][2];
#pragma unroll
            for (int mi = 0; mi < 4; mi++) {
                int r = m0 + mi * 16 + (lane & 15);
                int ccol = koff + (lane >> 4) * 8;
                ldsm4(a[mi], as_base + (unsigned)(r * LSTRIDE + ccol) * 2u);
            }
#pragma unroll
            for (int ni = 0; ni < 4; ni++) {
                int r = n0w + ni * 8 + (lane & 7);
                int ccol = koff + ((lane >> 3) & 1) * 8;
                ldsm2(b[ni], bs_base + (unsigned)(r * LSTRIDE + ccol) * 2u);
            }
#pragma unroll
            for (int mi = 0; mi < 4; mi++)
#pragma unroll
                for (int ni = 0; ni < 4; ni++) mma16816(c[mi][ni], a[mi], b[ni]);
        }
    }
    __syncthreads();

    const int gid = lane >> 2, tig = lane & 3;
#pragma unroll
    for (int mi = 0; mi < 4; mi++) {
        int r0 = m0 + mi * 16 + gid;
        int r1 = r0 + 8;
        int t0 = stgt[r0], t1 = stgt[r1];
        float s0 = 0.f, s1 = 0.f;
#pragma unroll
        for (int ni = 0; ni < 4; ni++) {
            int n = nblk0 + n0w + ni * 8 + tig * 2;
            float b0 = out_b[n], b1 = out_b[n + 1];
            float l00 = c[mi][ni][0] + b0, l01 = c[mi][ni][1] + b1;
            float l10 = c[mi][ni][2] + b0, l11 = c[mi][ni][3] + b1;
            s0 += __expf(l00) + __expf(l01);
            s1 += __expf(l10) + __expf(l11);
            if (n == t0) g_tgtlogit[r0] = l00;
            if (n + 1 == t0) g_tgtlogit[r0] = l01;
            if (n == t1) g_tgtlogit[r1] = l10;
            if (n + 1 == t1) g_tgtlogit[r1] = l11;
        }
        s0 += __shfl_xor_sync(0xffffffffu, s0, 1);
        s0 += __shfl_xor_sync(0xffffffffu, s0, 2);
        s1 += __shfl_xor_sync(0xffffffffu, s1, 1);
        s1 += __shfl_xor_sync(0xffffffffu, s1, 2);
        if (tig == 0) { red[r0 * 4 + warp_n] = s0; red[r1 * 4 + warp_n] = s1; }
    }
    __syncthreads();
    if (tid < 128)
        g_part[tl * Bq + tid] = red[tid * 4] + red[tid * 4 + 1] + red[tid * 4 + 2] + red[tid * 4 + 3];
}

// ============================================================
// generic 128x128 tile: out(fp32 or bf16) = A@W^T (+bias), pipelined
// ============================================================
__device__ void tile128_body(
    const __nv_bfloat16* A, const __nv_bfloat16* W, int ldw, int wrow0,
    const float* bias, int biasOff,
    float* outF, long outStride, long outOff,
    __nv_bfloat16* As, __nv_bfloat16* Bs)
{
    const int tid = threadIdx.x, lane = tid & 31, wid = tid >> 5;
    const int m0 = (wid >> 2) * 64, warp_n = wid & 3;

    float c[4][4][4];
#pragma unroll
    for (int mi = 0; mi < 4; mi++)
#pragma unroll
        for (int ni = 0; ni < 4; ni++)
#pragma unroll
            for (int q = 0; q < 4; q++) c[mi][ni][q] = 0.f;

    const unsigned as_base = (unsigned)__cvta_generic_to_shared(As);
    const unsigned bs_base = (unsigned)__cvta_generic_to_shared(Bs);
    const int ldrow = tid >> 3, ldc8 = (tid & 7) * 8;

    uint4 ra[4], rb[4];
    auto fetch = [&](int kc) {
        int k0 = kc * 64;
#pragma unroll
        for (int q = 0; q < 4; q++) {
            int row = q * 32 + ldrow;
            ra[q] = *reinterpret_cast<const uint4*>(&A[(long)row * 512 + k0 + ldc8]);
            rb[q] = *reinterpret_cast<const uint4*>(&W[(long)(wrow0 + row) * ldw + k0 + ldc8]);
        }
    };
    fetch(0);
    for (int kc = 0; kc < 8; kc++) {
        __syncthreads();
#pragma unroll
        for (int q = 0; q < 4; q++) {
            int row = q * 32 + ldrow;
            *reinterpret_cast<uint4*>(&As[row * LSTRIDE + ldc8]) = ra[q];
            *reinterpret_cast<uint4*>(&Bs[row * LSTRIDE + ldc8]) = rb[q];
        }
        __syncthreads();
        if (kc + 1 < 8) fetch(kc + 1);
#pragma unroll
        for (int ks = 0; ks < 4; ks++) {
            int koff = ks * 16;
            unsigned a[4][4], b[4][2];
#pragma unroll
            for (int mi = 0; mi < 4; mi++) {
                int r = m0 + mi * 16 + (lane & 15);
                int ccol = koff + (lane >> 4) * 8;
                ldsm4(a[mi], as_base + (unsigned)(r * LSTRIDE + ccol) * 2u);
            }
#pragma unroll
            for (int ni = 0; ni < 4; ni++) {
                int r = warp_n * 32 + ni * 8 + (lane & 7);
                int ccol = koff + ((lane >> 3) & 1) * 8;
                ldsm2(b[ni], bs_base + (unsigned)(r * LSTRIDE + ccol) * 2u);
            }
#pragma unroll
            for (int mi = 0; mi < 4; mi++)
#pragma unroll
                for (int ni = 0; ni < 4; ni++) mma16816(c[mi][ni], a[mi], b[ni]);
        }
    }

#pragma unroll
    for (int mi = 0; mi < 4; mi++)
#pragma unroll
        for (int ni = 0; ni < 4; ni++)
#pragma unroll
            for (int t2 = 0; t2 < 2; t2++) {
                int gm = m0 + mi * 16 + (lane >> 2) + 8 * t2;
#pragma unroll
                for (int u = 0; u < 2; u++) {
                    int n = warp_n * 32 + ni * 8 + 2 * (lane & 3) + u;
                    float v = c[mi][ni][2 * t2 + u];
                    if (bias) v += bias[biasOff + n];
                    outF[outOff + (long)gm * outStride + n] = v;
                }
            }
}

// ============================================================
// hid h-part tile: g_avf[:, nblk0:+128] = dh@hidW_left^T + hid_b
// ============================================================
__device__ void hidL_body(
    int nblk0, const __nv_bfloat16* A, const float* hid_b,
    __nv_bfloat16* As, __nv_bfloat16* Bs)
{
    tile128_body(A, g_hidWb, 1024, nblk0, hid_b, nblk0, g_avf, Hq, nblk0, As, Bs);
}

// ============================================================
// encoder wavefront + GV riders:
// blocks 0-15 layer0(t0), 16-31 layer1(t1), 32-43 GV tiles
// ============================================================
__global__ __launch_bounds__(256) void enc_wave_k(
    int t0, int t1, int tl, const int* __restrict__ src_lens,
    const float* __restrict__ enc_b1, const float* __restrict__ dec_b)
{
    __shared__ __nv_bfloat16 As[128 * LSTRIDE];
    __shared__ __nv_bfloat16 Bs[128 * LSTRIDE];
    const int nbase = (blockIdx.x & 15) * 32;
    if (blockIdx.x < 16) {
        if (t0 < 0) return;
        int p = t0 & 1;
        gates_body(nbase, g_h1b[p], g_Whh0b, 512,
                   nullptr, nullptr, 0, 1,
                   g_G0 + (long)t0 * G4, (long)Lq * G4, nullptr, src_lens, t0,
                   g_h1b[p], g_h1b[1 - p], g_c1, g_nh1b, nullptr, nullptr, As, Bs);
    } else if (blockIdx.x < 32) {
        if (t1 < 0) return;
        int p = t1 & 1;
        gates_body(nbase, g_nh1b, g_Wih1b, 512,
                   g_h2b[p], g_Whh1b, 512, 2,
                   nullptr, 0, enc_b1, src_lens, t1,
                   g_h2b[p], g_h2b[1 - p], g_c2, nullptr, g_S, nullptr, As, Bs);
    } else {
        // GV rider: tile idx = tl*12 + (blk-32)
        int idx = tl * 12 + (int)blockIdx.x - 32;
        if (idx >= GVTILES || tl < 0) return;
        int mt = idx >> 4, nt = idx & 15;
        tile128_body(g_vembB + (long)mt * 128 * 512, g_dWihb, 1024, nt * 128,
                     dec_b, nt * 128,
                     g_GV, G4, (long)mt * 128 * G4 + nt * 128, As, Bs);
    }
}

// ============================================================
// decoder main: blocks 0-15 gates(s), 16-140 logits(s-1) x2 tiles
// ============================================================
__global__ __launch_bounds__(256) void dec_main_k(
    int s, const int* __restrict__ trg_tokens, const float* __restrict__ out_b)
{
    __shared__ __nv_bfloat16 As[128 * LSTRIDE];
    __shared__ __nv_bfloat16 Bs[128 * LSTRIDE];
    __shared__ int stgt[128];
    __shared__ float red[512];
    if (blockIdx.x < 16) {
        if (s > Tq - 2) return;
        int p = s & 1;
        gates_body(blockIdx.x * 32,
                   g_avh[p], g_dWihb + 512, 1024,
                   g_dhb[p], g_dWhhb, 512, 2,
                   g_GV + (long)s * Bq * G4, (long)G4, nullptr, nullptr, 0,
                   g_dhb[p], g_dhb[1 - p], g_dc, nullptr, nullptr, g_dh, As, Bs);
    } else {
        int ls = s - 1;
        if (ls < 0) return;
        int lb = blockIdx.x - 16;
#pragma unroll
        for (int w = 0; w < 2; w++) {
            int tl = lb + LHALF * w;
            if (tl < NTILES)
                logits_body(tl, ls, g_avh[s & 1], out_b, trg_tokens, As, Bs, stgt, red);
        }
    }
}

// ============================================================
// attn (0-127) + combine(s-1) (128) + hid h-part (129-132)
// ============================================================
__global__ __launch_bounds__(256) void attn_combine_k(
    int s, const int* __restrict__ src_lens, const int* __restrict__ trg_lens,
    const float* __restrict__ hid_b)
{
    __shared__ __align__(16) char raw[36864];
    int tid = threadIdx.x;
    if (blockIdx.x < 128) {
        if (s > Tq - 2) return;
        float* sh = (float*)raw;
        float* part = sh + 512;
        float* sc = part + 256;
        float* sinv = sc + 64;
        int b = blockIdx.x;
        sh[tid] = g_dh[(long)b * Hq + tid];
        sh[tid + 256] = g_dh[(long)b * Hq + tid + 256];
        __syncthreads();
        int l = tid >> 2, q = tid & 3;
        const float* Sb = g_S + (long)b * Lq * Hq + (long)l * Hq + q * 128;
        float pv = 0.f;
#pragma unroll 8
        for (int k = 0; k < 128; k++) pv = fmaf(sh[q * 128 + k], Sb[k], pv);
        part[l * 4 + q] = pv;
        __syncthreads();
        if (tid < Lq) {
            float sv = part[tid * 4] + part[tid * 4 + 1] + part[tid * 4 + 2] + part[tid * 4 + 3];
            if (tid >= src_lens[b]) sv = -1e9f;
            sc[tid] = __expf(sv);
        }
        __syncthreads();
        if (tid < 32) {
            float v = sc[tid] + sc[tid + 32];
            v += __shfl_down_sync(0xffffffffu, v, 16);
            v += __shfl_down_sync(0xffffffffu, v, 8);
            v += __shfl_down_sync(0xffffffffu, v, 4);
            v += __shfl_down_sync(0xffffffffu, v, 2);
            v += __shfl_down_sync(0xffffffffu, v, 1);
            if (tid == 0) *sinv = __fdividef(1.f, v);
        }
        __syncthreads();
        if (tid < Lq) sc[tid] *= *sinv;
        __syncthreads();
        for (int j = tid; j < Hq; j += 256) {
            const float* Sb2 = g_S + (long)b * Lq * Hq + j;
            float acc = 0.f;
#pragma unroll 8
            for (int l2 = 0; l2 < Lq; l2++) acc = fmaf(sc[l2], Sb2[(long)l2 * Hq], acc);
            g_ctxb[(long)b * Hq + j] = __float2bfloat16_rn(acc);
        }
    } else if (blockIdx.x == 128) {
        int ls = s - 1;
        if (ls < 0) return;
        int b = tid;
        if (b < 128) {
            float tot = 0.f;
            for (int i = 0; i < NTILES; i++) tot += g_part[i * Bq + b];
            float nll = logf(tot) - g_tgtlogit[b];
            g_nllbuf[ls * Bq + b] = ((ls + 1) < trg_lens[b]) ? -nll : 0.f;
        }
    } else {
        if (s > Tq - 2) return;
        __nv_bfloat16* As = (__nv_bfloat16*)raw;
        __nv_bfloat16* Bs = As + 128 * LSTRIDE;
        hidL_body((blockIdx.x - 129) * 128, g_dhb[(s + 1) & 1], hid_b, As, Bs);
    }
}

// ============================================================
// standalone bf16 GEMM (pipelined, optional init)
// ============================================================
__global__ __launch_bounds__(256) void hgemm_k(
    const __nv_bfloat16* __restrict__ A0, const __nv_bfloat16* __restrict__ W0, int ldw0,
    const __nv_bfloat16* __restrict__ A1, const __nv_bfloat16* __restrict__ W1, int ldw1,
    int npairs,
    const float* __restrict__ initp,
    const float* __restrict__ bias, int N,
    float* __restrict__ outRaw, float* __restrict__ outTanhF,
    __nv_bfloat16* __restrict__ outBF)
{
    __shared__ __nv_bfloat16 As[128 * LSTRIDE];
    __shared__ __nv_bfloat16 Bs[128 * LSTRIDE];
    const int tid = threadIdx.x, lane = tid & 31, wid = tid >> 5;
    const int m0 = (wid >> 2) * 64, warp_n = wid & 3;
    const int mblk0 = blockIdx.x * 128, nblk0 = blockIdx.y * 128;

    float c[4][4][4];
#pragma unroll
    for (int mi = 0; mi < 4; mi++)
#pragma unroll
        for (int ni = 0; ni < 4; ni++)
#pragma unroll
            for (int q = 0; q < 4; q++) c[mi][ni][q] = 0.f;

    const unsigned as_base = (unsigned)__cvta_generic_to_shared(As);
    const unsigned bs_base = (unsigned)__cvta_generic_to_shared(Bs);
    const int ldrow = tid >> 3, ldc8 = (tid & 7) * 8;

    uint4 ra[4], rb[4];
    const int total = npairs * 8;
    auto fetch = [&](int ch) {
        int p = ch >> 3, k0 = (ch & 7) * 64;
        const __nv_bfloat16* A = (p == 0) ? A0 : A1;
        const __nv_bfloat16* W = (p == 0) ? W0 : W1;
        int ldw = (p == 0) ? ldw0 : ldw1;
#pragma unroll
        for (int q = 0; q < 4; q++) {
            int row = q * 32 + ldrow;
            int gm = mblk0 + row;
            ra[q] = *reinterpret_cast<const uint4*>(&A[(long)gm * 512 + k0 + ldc8]);
            rb[q] = *reinterpret_cast<const uint4*>(&W[(long)(nblk0 + row) * ldw + k0 + ldc8]);
        }
    };
    fetch(0);
    for (int ch = 0; ch < total; ch++) {
        __syncthreads();
#pragma unroll
        for (int q = 0; q < 4; q++) {
            int row = q * 32 + ldrow;
            *reinterpret_cast<uint4*>(&As[row * LSTRIDE + ldc8]) = ra[q];
            *reinterpret_cast<uint4*>(&Bs[row * LSTRIDE + ldc8]) = rb[q];
        }
        __syncthreads();
        if (ch + 1 < total) fetch(ch + 1);
#pragma unroll
        for (int ks = 0; ks < 4; ks++) {
            int koff = ks * 16;
            unsigned a[4][4], b[4][2];
#pragma unroll
            for (int mi = 0; mi < 4; mi++) {
                int r = m0 + mi * 16 + (lane & 15);
                int ccol = koff + (lane >> 4) * 8;
                ldsm4(a[mi], as_base + (unsigned)(r * LSTRIDE + ccol) * 2u);
            }
#pragma unroll
            for (int ni = 0; ni < 4; ni++) {
                int r = warp_n * 32 + ni * 8 + (lane & 7);
                int ccol = koff + ((lane >> 3) & 1) * 8;
                ldsm2(b[ni], bs_base + (unsigned)(r * LSTRIDE + ccol) * 2u);
            }
#pragma unroll
            for (int mi = 0; mi < 4; mi++)
#pragma unroll
                for (int ni = 0; ni < 4; ni++) mma16816(c[mi][ni], a[mi], b[ni]);
        }
    }

#pragma unroll
    for (int mi = 0; mi < 4; mi++)
#pragma unroll
        for (int ni = 0; ni < 4; ni++)
#pragma unroll
            for (int t2 = 0; t2 < 2; t2++) {
                int gm = mblk0 + m0 + mi * 16 + (lane >> 2) + 8 * t2;
#pragma unroll
                for (int u = 0; u < 2; u++) {
                    int n = nblk0 + warp_n * 32 + ni * 8 + 2 * (lane & 3) + u;
                    float v = c[mi][ni][2 * t2 + u];
                    long oi = (long)gm * N + n;
                    if (initp) v += initp[oi];
                    if (bias) v += bias[n];
                    if (outRaw) outRaw[oi] = v;
                    float tv = v;
                    if (outTanhF) { tv = tanhf(v); outTanhF[oi] = tv; }
                    if (outBF) outBF[oi] = __float2bfloat16_rn(outTanhF ? tv : v);
                }
            }
}

// ---------------- vectorized f2bf (8 elem/thread) ----------------
__device__ __forceinline__ void cvt8(const float* __restrict__ src,
                                     __nv_bfloat16* __restrict__ dst, long i)
{
    float4 v0 = *reinterpret_cast<const float4*>(src + i);
    float4 v1 = *reinterpret_cast<const float4*>(src + i + 4);
    __nv_bfloat162 r0 = __floats2bfloat162_rn(v0.x, v0.y);
    __nv_bfloat162 r1 = __floats2bfloat162_rn(v0.z, v0.w);
    __nv_bfloat162 r2 = __floats2bfloat162_rn(v1.x, v1.y);
    __nv_bfloat162 r3 = __floats2bfloat162_rn(v1.z, v1.w);
    uint4 o;
    o.x = *reinterpret_cast<unsigned*>(&r0);
    o.y = *reinterpret_cast<unsigned*>(&r1);
    o.z = *reinterpret_cast<unsigned*>(&r2);
    o.w = *reinterpret_cast<unsigned*>(&r3);
    *reinterpret_cast<uint4*>(dst + i) = o;
}

// 4 encoder weight matrices, 1M elements each; 512 blocks/segment
__global__ void f2bf_enc_k(const float* w0, const float* w1,
                           const float* w2, const float* w3)
{
    int seg = blockIdx.x >> 9;
    long i = ((long)(blockIdx.x & 511) * 256 + threadIdx.x) * 8;
    const float* srcs[4] = {w0, w1, w2, w3};
    __nv_bfloat16* dsts[4] = {g_Wih0b, g_Whh0b, g_Wih1b, g_Whh1b};
    cvt8(srcs[seg], dsts[seg], i);
}

// dec weights: dWih(1024), dWhh(512), hidW(256), initW(256), outW(8000) blocks
__global__ void f2bf_dec_k(const float* dWih, const float* dWhh,
                           const float* hidW, const float* initW, const float* outW)
{
    int b = blockIdx.x;
    const float* src; __nv_bfloat16* dst; int rb;
    if (b < 1024)      { src = dWih;  dst = g_dWihb;  rb = b; }
    else if (b < 1536) { src = dWhh;  dst = g_dWhhb;  rb = b - 1024; }
    else if (b < 1792) { src = hidW;  dst = g_hidWb;  rb = b - 1536; }
    else if (b < 2048) { src = initW; dst = g_initWb; rb = b - 1792; }
    else               { src = outW;  dst = g_outWb;  rb = b - 2048; }
    long i = ((long)rb * 256 + threadIdx.x) * 8;
    cvt8(src, dst, i);
}

// ---------------- gather-convert ----------------
__global__ void gather_src_k(const float* __restrict__ emb, const int* __restrict__ toks)
{
    int m = blockIdx.x;
    int tok = toks[m];
    const float2* src = reinterpret_cast<const float2*>(emb + (long)tok * Eq);
    __nv_bfloat162* dst = reinterpret_cast<__nv_bfloat162*>(g_xsB + (long)m * Eq);
    float2 v = src[threadIdx.x];
    dst[threadIdx.x] = __floats2bfloat162_rn(v.x, v.y);
}
__global__ void gather_trg_k(const float* __restrict__ emb, const int* __restrict__ toks)
{
    int m = blockIdx.x;
    int s = m >> 7, b = m & 127;
    int tok = toks[b * Tq + s];
    const float2* src = reinterpret_cast<const float2*>(emb + (long)tok * Eq);
    __nv_bfloat162* dst = reinterpret_cast<__nv_bfloat162*>(g_vembB + (long)m * Eq);
    float2 v = src[threadIdx.x];
    dst[threadIdx.x] = __floats2bfloat162_rn(v.x, v.y);
}

// ---------------- misc ----------------
__global__ void zero_k()
{
    int i = blockIdx.x * 256 + threadIdx.x;
    if (i < HB) {
        g_h1b[0][i] = __float2bfloat16(0.f);
        g_h2b[0][i] = __float2bfloat16(0.f);
        g_avh[0][i] = __float2bfloat16(0.f);
        g_c1[i] = 0.f; g_c2[i] = 0.f;
    }
}

// convert c1,c2 to bf16 in one launch
__global__ void conv_c_k()
{
    int i = blockIdx.x * 256 + threadIdx.x;
    if (i < HB) {
        g_c1b[i] = __float2bfloat16_rn(g_c1[i]);
        g_c2b[i] = __float2bfloat16_rn(g_c2[i]);
    }
}

__global__ __launch_bounds__(256) void reduce_k(float* __restrict__ out)
{
    __shared__ float sm[256];
    float t = 0.f;
    for (int i = threadIdx.x; i < (Tq - 1) * Bq; i += 256) t += g_nllbuf[i];
    sm[threadIdx.x] = t;
    __syncthreads();
    for (int st = 128; st > 0; st >>= 1) {
        if (threadIdx.x < st) sm[threadIdx.x] += sm[threadIdx.x + st];
        __syncthreads();
    }
    if (threadIdx.x == 0) out[0] = sm[0];
}

// ---------------- launch ----------------
extern "C" void kernel_launch(void* const* d_in, const int* in_sizes, int n_in,
                              void* d_out, int out_size)
{
    const int*   src_tokens = (const int*)d_in[0];
    const int*   src_lens   = (const int*)d_in[1];
    const int*   trg_tokens = (const int*)d_in[2];
    const int*   trg_lens   = (const int*)d_in[3];
    const float* src_emb    = (const float*)d_in[4];
    const float* trg_emb    = (const float*)d_in[5];
    const float* enc_Wih0   = (const float*)d_in[6];
    const float* enc_Whh0   = (const float*)d_in[7];
    const float* enc_b0     = (const float*)d_in[8];
    const float* enc_Wih1   = (const float*)d_in[9];
    const float* enc_Whh1   = (const float*)d_in[10];
    const float* enc_b1     = (const float*)d_in[11];
    const float* dec_Wih    = (const float*)d_in[12];
    const float* dec_Whh    = (const float*)d_in[13];
    const float* dec_b      = (const float*)d_in[14];
    const float* hid_W      = (const float*)d_in[15];
    const float* hid_b      = (const float*)d_in[16];
    const float* out_W      = (const float*)d_in[17];
    const float* out_b      = (const float*)d_in[18];
    const float* init_W     = (const float*)d_in[19];
    const float* init_b     = (const float*)d_in[20];

    float *G0, *dc, *dh;
    __nv_bfloat16 *Wih0b, *initWb, *c1b, *c2b, *dhb0, *ctxb, *avh0, *xsB;
    cudaGetSymbolAddress((void**)&G0, g_G0);
    cudaGetSymbolAddress((void**)&dc, g_dc);
    cudaGetSymbolAddress((void**)&dh, g_dh);
    cudaGetSymbolAddress((void**)&Wih0b, g_Wih0b);
    cudaGetSymbolAddress((void**)&initWb, g_initWb);
    cudaGetSymbolAddress((void**)&c1b, g_c1b);
    cudaGetSymbolAddress((void**)&c2b, g_c2b);
    cudaGetSymbolAddress((void**)&dhb0, g_dhb);
    cudaGetSymbolAddress((void**)&ctxb, g_ctxb);
    cudaGetSymbolAddress((void**)&avh0, g_avh);
    cudaGetSymbolAddress((void**)&xsB, g_xsB);
    __nv_bfloat16* dhb[2] = {dhb0, dhb0 + HB};
    __nv_bfloat16* avh[2] = {avh0, avh0 + HB};

    const int cb = (HB + 255) / 256;

    // ordered so launch #6 (ncu -s 5 -c 1) is the G0 HMMA GEMM
    zero_k<<<cb, 256>>>();                                     // 1
    gather_src_k<<<Bq * Lq, 256>>>(src_emb, src_tokens);       // 2
    gather_trg_k<<<(Tq - 1) * Bq, 256>>>(trg_emb, trg_tokens); // 3
    f2bf_enc_k<<<2048, 256>>>(enc_Wih0, enc_Whh0, enc_Wih1, enc_Whh1); // 4
    f2bf_dec_k<<<10048, 256>>>(dec_Wih, dec_Whh, hid_W, init_W, out_W); // 5

    // 6: G0 = xs @ Wih0^T + b0   (M=8192, N=2048)  <- profiled
    hgemm_k<<<dim3(Bq * Lq / 128, G4 / 128), 256>>>(
        xsB, Wih0b, KP, nullptr, nullptr, 0, 1,
        nullptr, enc_b0, G4, G0, nullptr, nullptr);

    // ---------------- encoder wavefront + GV riders ----------------
    for (int t = 0; t <= Lq; t++)
        enc_wave_k<<<44, 256>>>(t < Lq ? t : -1, t - 1, t, src_lens, enc_b1, dec_b);

    // decoder init: c0 = [c1,c2] @ init_W^T + init_b ; h0 = tanh(c0)
    conv_c_k<<<cb, 256>>>();
    hgemm_k<<<dim3(1, Hq / 128), 256>>>(
        c1b, initWb, 1024, c2b, initWb + 512, 1024, 2,
        nullptr, init_b, Hq, dc, dh, dhb[0]);

    // ---------------- decoder ----------------
    for (int s = 0; s < Tq - 1; s++) {
        dec_main_k<<<16 + LHALF, 256>>>(s, trg_tokens, out_b);
        attn_combine_k<<<133, 256>>>(s, src_lens, trg_lens, hid_b);
        hgemm_k<<<dim3(1, Hq / 128), 256>>>(
            ctxb, g_hidWb + 512, 1024, nullptr, nullptr, 0, 1,
            g_avf, nullptr, Hq, nullptr, nullptr, avh[(s + 1) & 1]);
    }
    // tail: logits(T-2) + combine(T-2)
    dec_main_k<<<16 + LHALF, 256>>>(Tq - 1, trg_tokens, out_b);
    attn_combine_k<<<133, 256>>>(Tq - 1, src_lens, trg_lens, hid_b);

    reduce_k<<<1, 256>>>((float*)d_out);
}